// round 10
// baseline (speedup 1.0000x reference)
#include <cuda_runtime.h>
#include <cuda_bf16.h>
#include <cstdint>

#define Nn 100000
#define Ee 3200000
#define Bb 64
#define FIN 64
#define EIN 16
#define ADIM 13
#define Hh 32
#define OUT 64
#define EPS_GEN 1e-7f
#define EPS_BN 1e-5f

#define TR 64                          // rows per block tile in node GEMMs
#define NBLK64 ((Nn + TR - 1) / TR)    // 1563
#define TRE 128                        // enc tile rows
#define NBLK128 ((Nn + TRE - 1) / TRE) // 782

#define SCAN_B 1024
#define NSCAN ((Nn + SCAN_B - 1) / SCAN_B)   // 98

// ---------------- scratch (device globals; no allocs allowed) ----------------
__device__ float  g_h[Nn * Hh];
__device__ float  g_esum[Nn * Hh];
__device__ float  g_wsum[Nn * Hh];
__device__ float  g_y1[Nn * OUT];
__device__ float  g_y2[Nn * OUT];
__device__ float  g_y3[Nn * OUT];
__device__ double g_stats[3 * 128];
__device__ float  g_pool[Bb * OUT];
__device__ float  g_cnt[Bb];
// sort-by-dst scratch
__device__ int    g_deg[Nn];
__device__ int    g_cur[Nn];
__device__ int    g_part[NSCAN];
__device__ int    g_partoff[NSCAN];
__device__ int2   g_epack[Ee];         // (edge id, src) sorted by dst
__device__ int    g_dsts[Ee];          // dst, sorted

// ---------------- helpers ----------------
__device__ __forceinline__ void red_add_v4(float* addr, float4 v) {
    asm volatile("red.global.add.v4.f32 [%0], {%1,%2,%3,%4};"
                 :: "l"(addr), "f"(v.x), "f"(v.y), "f"(v.z), "f"(v.w) : "memory");
}

__device__ __forceinline__ void fma_row(float4& acc, float zv, float4 wv) {
    acc.x = fmaf(zv, wv.x, acc.x);
    acc.y = fmaf(zv, wv.y, acc.y);
    acc.z = fmaf(zv, wv.z, acc.z);
    acc.w = fmaf(zv, wv.w, acc.w);
}

__device__ __forceinline__ float4 shfl_up4(float4 v, int off) {
    float4 r;
    r.x = __shfl_up_sync(0xffffffffu, v.x, off);
    r.y = __shfl_up_sync(0xffffffffu, v.y, off);
    r.z = __shfl_up_sync(0xffffffffu, v.z, off);
    r.w = __shfl_up_sync(0xffffffffu, v.w, off);
    return r;
}

// ---------------- 0: zero scratch ----------------
__global__ void zero_kernel() {
    int idx = blockIdx.x * blockDim.x + threadIdx.x;
    int stride = gridDim.x * blockDim.x;
    const int n4 = (Nn * Hh) / 4;
    float4 z4 = make_float4(0.f, 0.f, 0.f, 0.f);
    for (int i = idx; i < n4; i += stride) {
        reinterpret_cast<float4*>(g_esum)[i] = z4;
        reinterpret_cast<float4*>(g_wsum)[i] = z4;
    }
    for (int i = idx; i < Nn; i += stride) g_deg[i] = 0;
    for (int i = idx; i < Bb * OUT; i += stride) g_pool[i] = 0.f;
    for (int i = idx; i < Bb; i += stride) g_cnt[i] = 0.f;
    for (int i = idx; i < 3 * 128; i += stride) g_stats[i] = 0.0;
}

// ---------------- 1: node encoder  h = x @ node_w + node_b  [N,64]->[N,32] ----
__global__ void __launch_bounds__(256) enc_kernel(const float* __restrict__ x,
                                                  const float* __restrict__ W,
                                                  const float* __restrict__ bias) {
    __shared__ __align__(16) float zs[FIN * (TRE + 1)];
    __shared__ __align__(16) float ws[FIN * Hh];
    int tid = threadIdx.x;
    int n0 = blockIdx.x * TRE;
    for (int i = tid; i < (FIN * Hh) / 4; i += 256)
        reinterpret_cast<float4*>(ws)[i] = reinterpret_cast<const float4*>(W)[i];
    #pragma unroll
    for (int it = 0; it < 8; it++) {
        int idx = tid + it * 256;
        int row = idx >> 4, k4 = idx & 15;
        int gn = n0 + row;
        float4 v = make_float4(0.f, 0.f, 0.f, 0.f);
        if (gn < Nn) v = *reinterpret_cast<const float4*>(x + (size_t)gn * FIN + 4 * k4);
        zs[(4*k4+0) * (TRE+1) + row] = v.x;
        zs[(4*k4+1) * (TRE+1) + row] = v.y;
        zs[(4*k4+2) * (TRE+1) + row] = v.z;
        zs[(4*k4+3) * (TRE+1) + row] = v.w;
    }
    __syncthreads();
    int lane = tid & 31, w = tid >> 5;
    int cg = w & 1;
    int rq = w >> 1;
    int rl = 32 * rq + lane;
    float4 a0 = {0,0,0,0}, a1 = {0,0,0,0}, a2 = {0,0,0,0}, a3 = {0,0,0,0};
    const float4* ws4 = reinterpret_cast<const float4*>(ws);
    #pragma unroll 8
    for (int k = 0; k < FIN; k++) {
        float z = zs[k * (TRE+1) + rl];
        const float4* wr = ws4 + k * 8 + cg * 4;
        fma_row(a0, z, wr[0]); fma_row(a1, z, wr[1]);
        fma_row(a2, z, wr[2]); fma_row(a3, z, wr[3]);
    }
    int gn = n0 + rl;
    if (gn < Nn) {
        const float4* b4 = reinterpret_cast<const float4*>(bias) + cg * 4;
        float4 vv;
        float* op = g_h + (size_t)gn * Hh + 16 * cg;
        vv = a0; vv.x += b4[0].x; vv.y += b4[0].y; vv.z += b4[0].z; vv.w += b4[0].w;
        *reinterpret_cast<float4*>(op + 0) = vv;
        vv = a1; vv.x += b4[1].x; vv.y += b4[1].y; vv.z += b4[1].z; vv.w += b4[1].w;
        *reinterpret_cast<float4*>(op + 4) = vv;
        vv = a2; vv.x += b4[2].x; vv.y += b4[2].y; vv.z += b4[2].z; vv.w += b4[2].w;
        *reinterpret_cast<float4*>(op + 8) = vv;
        vv = a3; vv.x += b4[3].x; vv.y += b4[3].y; vv.z += b4[3].z; vv.w += b4[3].w;
        *reinterpret_cast<float4*>(op + 12) = vv;
    }
}

// ---------------- 2a: histogram of dst ----------------------------------------
__global__ void hist_kernel(const int* __restrict__ ei) {
    int idx = blockIdx.x * blockDim.x + threadIdx.x;
    int stride = gridDim.x * blockDim.x;
    for (int e = idx; e < Ee; e += stride)
        atomicAdd(&g_deg[ei[Ee + e]], 1);
}

// ---------------- 2b: per-block partial sums ----------------------------------
__global__ void __launch_bounds__(SCAN_B) scan1_kernel() {
    __shared__ int sred[32];
    int t = threadIdx.x;
    int i = blockIdx.x * SCAN_B + t;
    int v = (i < Nn) ? g_deg[i] : 0;
    #pragma unroll
    for (int o = 16; o; o >>= 1) v += __shfl_down_sync(0xffffffffu, v, o);
    int warp = t >> 5, lane = t & 31;
    if (lane == 0) sred[warp] = v;
    __syncthreads();
    if (warp == 0) {
        v = sred[lane];
        #pragma unroll
        for (int o = 16; o; o >>= 1) v += __shfl_down_sync(0xffffffffu, v, o);
        if (lane == 0) g_part[blockIdx.x] = v;
    }
}

// ---------------- 2c: scan block partials (1 block) ---------------------------
__global__ void __launch_bounds__(128) scan2_kernel() {
    __shared__ int s[128];
    int t = threadIdx.x;
    int v = (t < NSCAN) ? g_part[t] : 0;
    s[t] = v;
    __syncthreads();
    #pragma unroll
    for (int o = 1; o < 128; o <<= 1) {
        int add = (t >= o) ? s[t - o] : 0;
        __syncthreads();
        s[t] += add;
        __syncthreads();
    }
    if (t < NSCAN) g_partoff[t] = s[t] - v;   // exclusive
}

// ---------------- 2d: per-block exclusive scan + add --------------------------
__global__ void __launch_bounds__(SCAN_B) scan3_kernel() {
    __shared__ int s[SCAN_B];
    int t = threadIdx.x;
    int i = blockIdx.x * SCAN_B + t;
    int v = (i < Nn) ? g_deg[i] : 0;
    s[t] = v;
    __syncthreads();
    #pragma unroll
    for (int o = 1; o < SCAN_B; o <<= 1) {
        int add = (t >= o) ? s[t - o] : 0;
        __syncthreads();
        s[t] += add;
        __syncthreads();
    }
    if (i < Nn) g_cur[i] = s[t] - v + g_partoff[blockIdx.x];
}

// ---------------- 2e: scatter edges into dst-sorted order ---------------------
__global__ void scatter_kernel(const int* __restrict__ ei) {
    int idx = blockIdx.x * blockDim.x + threadIdx.x;
    int stride = gridDim.x * blockDim.x;
    for (int e = idx; e < Ee; e += stride) {
        int dst = ei[Ee + e];
        int src = ei[e];
        int slot = atomicAdd(&g_cur[dst], 1);
        g_epack[slot] = make_int2(e, src);
        g_dsts[slot] = dst;
    }
}

// ---------------- 2f: edge pass on sorted edges + segmented reduction ---------
__global__ void __launch_bounds__(256) edge_kernel(const float* __restrict__ eattr,
                                                   const float* __restrict__ ew,
                                                   const float* __restrict__ eb) {
    __shared__ __align__(16) float sattr[32 * 20];
    __shared__ __align__(16) float sws[EIN * Hh];   // 16x32
    int tid = threadIdx.x;
    for (int i = tid; i < EIN * Hh; i += 256) sws[i] = ew[i];
    int j = tid & 7;          // feature quad (feats 4j..4j+3)
    int el = tid >> 3;        // edge within tile (0..31)
    int lane = tid & 31;
    float4 eb4 = *reinterpret_cast<const float4*>(eb + 4*j);
    const float4* w4p = reinterpret_cast<const float4*>(sws); // [k][8]
    const int ntiles = Ee / 32;
    for (int t = blockIdx.x; t < ntiles; t += gridDim.x) {
        int e0 = t * 32;
        // per-thread reads (8 lanes share each 12B record; L1 broadcast)
        int2 pk = g_epack[e0 + el];        // (eid, src)
        int   d = g_dsts[e0 + el];
        __syncthreads();
        {
            // gather this edge's 16 attrs: 8 lanes x float2, one 64B seg per edge
            float2 a2 = *reinterpret_cast<const float2*>(
                eattr + (size_t)pk.x * EIN + 2 * j);
            sattr[el * 20 + 2*j]     = a2.x;
            sattr[el * 20 + 2*j + 1] = a2.y;
        }
        __syncthreads();
        float4 ea = eb4;
        const float4* a4p = reinterpret_cast<const float4*>(sattr + el * 20);
        #pragma unroll
        for (int k4 = 0; k4 < 4; k4++) {
            float4 a4 = a4p[k4];
            float4 w0 = w4p[(4*k4+0)*8 + j];
            float4 w1 = w4p[(4*k4+1)*8 + j];
            float4 w2 = w4p[(4*k4+2)*8 + j];
            float4 w3 = w4p[(4*k4+3)*8 + j];
            fma_row(ea, a4.x, w0); fma_row(ea, a4.y, w1); fma_row(ea, a4.z, w2); fma_row(ea, a4.w, w3);
        }
        float4 hv = *reinterpret_cast<const float4*>(g_h + (size_t)pk.y * Hh + 4*j);
        float4 m;
        m.x = fmaxf(hv.x + ea.x, 0.f) + EPS_GEN;
        m.y = fmaxf(hv.y + ea.y, 0.f) + EPS_GEN;
        m.z = fmaxf(hv.z + ea.z, 0.f) + EPS_GEN;
        m.w = fmaxf(hv.w + ea.w, 0.f) + EPS_GEN;
        float4 P;
        P.x = __expf(m.x); P.y = __expf(m.y); P.z = __expf(m.z); P.w = __expf(m.w);
        float4 WP = make_float4(m.x*P.x, m.y*P.y, m.z*P.z, m.w*P.w);
        // segmented inclusive scan over the 4 edge-groups (8 lanes each)
        {
            int dp = __shfl_up_sync(0xffffffffu, d, 8);
            float4 Pp = shfl_up4(P, 8), Wp = shfl_up4(WP, 8);
            if (lane >= 8 && dp == d) {
                P.x += Pp.x; P.y += Pp.y; P.z += Pp.z; P.w += Pp.w;
                WP.x += Wp.x; WP.y += Wp.y; WP.z += Wp.z; WP.w += Wp.w;
            }
            int dp2 = __shfl_up_sync(0xffffffffu, d, 16);
            float4 Pq = shfl_up4(P, 16), Wq = shfl_up4(WP, 16);
            if (lane >= 16 && dp2 == d) {
                P.x += Pq.x; P.y += Pq.y; P.z += Pq.z; P.w += Pq.w;
                WP.x += Wq.x; WP.y += Wq.y; WP.z += Wq.z; WP.w += Wq.w;
            }
        }
        int dn = __shfl_down_sync(0xffffffffu, d, 8);
        bool tail = (lane >= 24) || (dn != d);
        if (tail) {
            red_add_v4(g_esum + (size_t)d * Hh + 4*j, P);
            red_add_v4(g_wsum + (size_t)d * Hh + 4*j, WP);
        }
        __syncthreads();
    }
}

// ---------------- node-GEMM consumer: thread = 1 row x 16 cols ----------------
template<int K>
__device__ __forceinline__ void gemm16(const float* zs, const float* ws,
                                       const float* bias, float4 a[4],
                                       int& gn, int& cg, int n0, int tid) {
    int lane = tid & 31, w = tid >> 5;
    cg = w & 3;                 // cols 16*cg..16*cg+15
    int rh = w >> 2;            // row half (TR=64)
    int rl = 32 * rh + lane;
    a[0] = make_float4(0,0,0,0); a[1] = make_float4(0,0,0,0);
    a[2] = make_float4(0,0,0,0); a[3] = make_float4(0,0,0,0);
    const float4* ws4 = reinterpret_cast<const float4*>(ws);
    #pragma unroll 8
    for (int k = 0; k < K; k++) {
        float z = zs[k * (TR+1) + rl];
        const float4* wr = ws4 + k * 16 + cg * 4;
        fma_row(a[0], z, wr[0]); fma_row(a[1], z, wr[1]);
        fma_row(a[2], z, wr[2]); fma_row(a[3], z, wr[3]);
    }
    const float4* b4 = reinterpret_cast<const float4*>(bias) + cg * 4;
    #pragma unroll
    for (int i = 0; i < 4; i++) {
        float4 bb = b4[i];
        a[i].x += bb.x; a[i].y += bb.y; a[i].z += bb.z; a[i].w += bb.w;
    }
    gn = n0 + rl;
}

__device__ __forceinline__ void store_stats16(float4 a[4], int gn, int cg, int lane,
                                              float* out, float* ssum, float* ssq) {
    bool ok = gn < Nn;
    float* op = out + (size_t)gn * OUT + 16 * cg;
    #pragma unroll
    for (int i = 0; i < 4; i++) {
        if (ok) *reinterpret_cast<float4*>(op + 4*i) = a[i];
        else a[i] = make_float4(0,0,0,0);
    }
    #pragma unroll
    for (int i = 0; i < 4; i++) {
        int q = ((lane & 3) + i) & 3;
        float4 s = a[q];
        int c = 16 * cg + 4 * q;
        atomicAdd(&ssum[c+0], s.x); atomicAdd(&ssum[c+1], s.y);
        atomicAdd(&ssum[c+2], s.z); atomicAdd(&ssum[c+3], s.w);
        atomicAdd(&ssq[c+0], s.x*s.x); atomicAdd(&ssq[c+1], s.y*s.y);
        atomicAdd(&ssq[c+2], s.z*s.z); atomicAdd(&ssq[c+3], s.w*s.w);
    }
}

// ---------------- 3: stage A  z = agg + h ; y1 = z@W1+b1 ; stats1 -------------
__global__ void __launch_bounds__(256) stageA_kernel(const float* __restrict__ W,
                                                     const float* __restrict__ bias) {
    __shared__ __align__(16) float zs[Hh * (TR + 1)];
    __shared__ __align__(16) float ws[Hh * OUT];
    __shared__ float ssum[64], ssq[64];
    int tid = threadIdx.x;
    int n0 = blockIdx.x * TR;
    for (int i = tid; i < (Hh * OUT) / 4; i += 256)
        reinterpret_cast<float4*>(ws)[i] = reinterpret_cast<const float4*>(W)[i];
    if (tid < 64) { ssum[tid] = 0.f; ssq[tid] = 0.f; }
    // loader: 64 rows x 8 k4 = 512 float4
    #pragma unroll
    for (int it = 0; it < 2; it++) {
        int idx = tid + it * 256;
        int row = idx >> 3, k4 = idx & 7;
        int gn = n0 + row;
        float4 z = make_float4(0,0,0,0);
        if (gn < Nn) {
            float4 es = *reinterpret_cast<const float4*>(g_esum + (size_t)gn * Hh + 4*k4);
            float4 wsu = *reinterpret_cast<const float4*>(g_wsum + (size_t)gn * Hh + 4*k4);
            float4 hv = *reinterpret_cast<const float4*>(g_h + (size_t)gn * Hh + 4*k4);
            z.x = ((es.x > 0.f) ? wsu.x / es.x : 0.f) + hv.x;
            z.y = ((es.y > 0.f) ? wsu.y / es.y : 0.f) + hv.y;
            z.z = ((es.z > 0.f) ? wsu.z / es.z : 0.f) + hv.z;
            z.w = ((es.w > 0.f) ? wsu.w / es.w : 0.f) + hv.w;
        }
        zs[(4*k4+0) * (TR+1) + row] = z.x;
        zs[(4*k4+1) * (TR+1) + row] = z.y;
        zs[(4*k4+2) * (TR+1) + row] = z.z;
        zs[(4*k4+3) * (TR+1) + row] = z.w;
    }
    __syncthreads();
    float4 a[4]; int gn, cg;
    gemm16<Hh>(zs, ws, bias, a, gn, cg, n0, tid);
    store_stats16(a, gn, cg, tid & 31, g_y1, ssum, ssq);
    __syncthreads();
    if (tid < 64) {
        atomicAdd(&g_stats[tid],      (double)ssum[tid]);
        atomicAdd(&g_stats[64 + tid], (double)ssq[tid]);
    }
}

// ---------------- 4: stages B/C  z=relu(bn(in)) ; out=z@W+b ; stats ------------
__global__ void __launch_bounds__(256) stageBC_kernel(const float* __restrict__ W,
                                                      const float* __restrict__ bias,
                                                      const float* __restrict__ gam,
                                                      const float* __restrict__ bet,
                                                      int sel) {
    __shared__ __align__(16) float zs[OUT * (TR + 1)];
    __shared__ __align__(16) float ws[OUT * OUT];
    __shared__ float ssum[64], ssq[64], sscale[64], sshift[64];
    const float* in  = sel ? g_y2 : g_y1;
    float*       out = sel ? g_y3 : g_y2;
    int sin  = sel ? 128 : 0;
    int sout = sel ? 256 : 128;
    int tid = threadIdx.x;
    int n0 = blockIdx.x * TR;
    for (int i = tid; i < (OUT * OUT) / 4; i += 256)
        reinterpret_cast<float4*>(ws)[i] = reinterpret_cast<const float4*>(W)[i];
    if (tid < 64) {
        double mean = g_stats[sin + tid] / (double)Nn;
        double msq  = g_stats[sin + 64 + tid] / (double)Nn;
        double var  = msq - mean * mean;
        float sc = gam[tid] * rsqrtf((float)var + EPS_BN);
        sscale[tid] = sc;
        sshift[tid] = bet[tid] - (float)mean * sc;
        ssum[tid] = 0.f; ssq[tid] = 0.f;
    }
    __syncthreads();
    // loader: 64 rows x 16 k4 = 1024 float4
    #pragma unroll
    for (int it = 0; it < 4; it++) {
        int idx = tid + it * 256;
        int row = idx >> 4, k4 = idx & 15;
        int gn = n0 + row;
        float4 v = make_float4(0,0,0,0);
        if (gn < Nn) v = *reinterpret_cast<const float4*>(in + (size_t)gn * OUT + 4*k4);
        zs[(4*k4+0) * (TR+1) + row] = fmaxf(sscale[4*k4+0] * v.x + sshift[4*k4+0], 0.f);
        zs[(4*k4+1) * (TR+1) + row] = fmaxf(sscale[4*k4+1] * v.y + sshift[4*k4+1], 0.f);
        zs[(4*k4+2) * (TR+1) + row] = fmaxf(sscale[4*k4+2] * v.z + sshift[4*k4+2], 0.f);
        zs[(4*k4+3) * (TR+1) + row] = fmaxf(sscale[4*k4+3] * v.w + sshift[4*k4+3], 0.f);
    }
    __syncthreads();
    float4 a[4]; int gn, cg;
    gemm16<OUT>(zs, ws, bias, a, gn, cg, n0, tid);
    store_stats16(a, gn, cg, tid & 31, out, ssum, ssq);
    __syncthreads();
    if (tid < 64) {
        atomicAdd(&g_stats[sout + tid],      (double)ssum[tid]);
        atomicAdd(&g_stats[sout + 64 + tid], (double)ssq[tid]);
    }
}

// ---------------- 5: stage D  node_out = relu(bn3(y3))@W4+b4, pooled -----------
__global__ void __launch_bounds__(256) stageD_kernel(const float* __restrict__ W,
                                                     const float* __restrict__ bias,
                                                     const float* __restrict__ gam,
                                                     const float* __restrict__ bet,
                                                     const int* __restrict__ batch) {
    __shared__ __align__(16) float zs[OUT * (TR + 1)];
    __shared__ __align__(16) float ws[OUT * OUT];
    __shared__ float sscale[64], sshift[64];
    int tid = threadIdx.x;
    int n0 = blockIdx.x * TR;
    for (int i = tid; i < (OUT * OUT) / 4; i += 256)
        reinterpret_cast<float4*>(ws)[i] = reinterpret_cast<const float4*>(W)[i];
    if (tid < 64) {
        double mean = g_stats[256 + tid] / (double)Nn;
        double msq  = g_stats[256 + 64 + tid] / (double)Nn;
        double var  = msq - mean * mean;
        float sc = gam[tid] * rsqrtf((float)var + EPS_BN);
        sscale[tid] = sc;
        sshift[tid] = bet[tid] - (float)mean * sc;
    }
    __syncthreads();
    #pragma unroll
    for (int it = 0; it < 4; it++) {
        int idx = tid + it * 256;
        int row = idx >> 4, k4 = idx & 15;
        int gn = n0 + row;
        float4 v = make_float4(0,0,0,0);
        if (gn < Nn) v = *reinterpret_cast<const float4*>(g_y3 + (size_t)gn * OUT + 4*k4);
        zs[(4*k4+0) * (TR+1) + row] = fmaxf(sscale[4*k4+0] * v.x + sshift[4*k4+0], 0.f);
        zs[(4*k4+1) * (TR+1) + row] = fmaxf(sscale[4*k4+1] * v.y + sshift[4*k4+1], 0.f);
        zs[(4*k4+2) * (TR+1) + row] = fmaxf(sscale[4*k4+2] * v.z + sshift[4*k4+2], 0.f);
        zs[(4*k4+3) * (TR+1) + row] = fmaxf(sscale[4*k4+3] * v.w + sshift[4*k4+3], 0.f);
    }
    __syncthreads();
    float4 a[4]; int gn, cg;
    gemm16<OUT>(zs, ws, bias, a, gn, cg, n0, tid);
    if (gn < Nn) {
        int g = batch[gn];
        float* pp = g_pool + (size_t)g * OUT + 16 * cg;
        #pragma unroll
        for (int i = 0; i < 4; i++) red_add_v4(pp + 4*i, a[i]);
        if (cg == 0) atomicAdd(&g_cnt[g], 1.0f);
    }
}

// ---------------- 6: head (per graph) -----------------------------------------
__global__ void head_kernel(const float* __restrict__ action,
                            const float* __restrict__ pinw, const float* __restrict__ pinb,
                            const float* __restrict__ phw,  const float* __restrict__ phb,
                            const float* __restrict__ pow_, const float* __restrict__ pob,
                            float* __restrict__ outp) {
    int g = threadIdx.x;
    if (g >= Bb) return;
    float inv = 1.0f / fmaxf(g_cnt[g], 1.0f);
    float fp[16];
    #pragma unroll
    for (int jj = 0; jj < 16; jj++) {
        float s = 0.f;
        for (int f = 0; f < OUT; f++) s += g_pool[g * OUT + f] * pinw[f * 16 + jj];
        fp[jj] = fmaxf(s * inv + pinb[jj], 0.f);
    }
    float res = pob[0];
    #pragma unroll
    for (int q = 0; q < 10; q++) {
        float s = phb[q];
        #pragma unroll
        for (int jj = 0; jj < 16; jj++) s += fp[jj] * phw[jj * 10 + q];
        #pragma unroll
        for (int a = 0; a < ADIM; a++) s += action[g * ADIM + a] * phw[(16 + a) * 10 + q];
        res += fmaxf(s, 0.f) * pow_[q];
    }
    outp[g] = res;
}

// ---------------- launch -------------------------------------------------------
extern "C" void kernel_launch(void* const* d_in, const int* in_sizes, int n_in,
                              void* d_out, int out_size) {
    const float* x      = (const float*)d_in[0];
    const int*   ei     = (const int*)  d_in[1];
    const float* eattr  = (const float*)d_in[2];
    const int*   batch  = (const int*)  d_in[3];
    const float* action = (const float*)d_in[4];
    const float* node_w = (const float*)d_in[5];
    const float* node_b = (const float*)d_in[6];
    const float* edge_w = (const float*)d_in[7];
    const float* edge_b = (const float*)d_in[8];
    const float* w1 = (const float*)d_in[9];  const float* b1 = (const float*)d_in[10];
    const float* g1 = (const float*)d_in[11]; const float* bb1 = (const float*)d_in[12];
    const float* w2 = (const float*)d_in[13]; const float* b2 = (const float*)d_in[14];
    const float* g2 = (const float*)d_in[15]; const float* bb2 = (const float*)d_in[16];
    const float* w3 = (const float*)d_in[17]; const float* b3 = (const float*)d_in[18];
    const float* g3 = (const float*)d_in[19]; const float* bb3 = (const float*)d_in[20];
    const float* w4 = (const float*)d_in[21]; const float* b4 = (const float*)d_in[22];
    const float* pinw = (const float*)d_in[23]; const float* pinb = (const float*)d_in[24];
    const float* phw  = (const float*)d_in[25]; const float* phb  = (const float*)d_in[26];
    const float* pow_ = (const float*)d_in[27]; const float* pob  = (const float*)d_in[28];

    zero_kernel<<<2048, 256>>>();
    enc_kernel<<<NBLK128, 256>>>(x, node_w, node_b);
    hist_kernel<<<2048, 256>>>(ei);
    scan1_kernel<<<NSCAN, SCAN_B>>>();
    scan2_kernel<<<1, 128>>>();
    scan3_kernel<<<NSCAN, SCAN_B>>>();
    scatter_kernel<<<2048, 256>>>(ei);
    edge_kernel<<<2048, 256>>>(eattr, edge_w, edge_b);
    stageA_kernel<<<NBLK64, 256>>>(w1, b1);
    stageBC_kernel<<<NBLK64, 256>>>(w2, b2, g1, bb1, 0);
    stageBC_kernel<<<NBLK64, 256>>>(w3, b3, g2, bb2, 1);
    stageD_kernel<<<NBLK64, 256>>>(w4, b4, g3, bb3, batch);
    head_kernel<<<1, 64>>>(action, pinw, pinb, phw, phb, pow_, pob, (float*)d_out);
}

// round 11
// speedup vs baseline: 1.1524x; 1.1524x over previous
#include <cuda_runtime.h>
#include <cuda_bf16.h>
#include <cstdint>

#define Nn 100000
#define Ee 3200000
#define Bb 64
#define FIN 64
#define EIN 16
#define ADIM 13
#define Hh 32
#define OUT 64
#define EPS_GEN 1e-7f
#define EPS_BN 1e-5f

#define TR 64                          // rows per block tile in node GEMMs
#define NBLK64 ((Nn + TR - 1) / TR)    // 1563
#define TRE 128                        // enc tile rows
#define NBLK128 ((Nn + TRE - 1) / TRE) // 782

// ---------------- scratch (device globals; no allocs allowed) ----------------
__device__ float  g_h[Nn * Hh];
__device__ float  g_esum[Nn * Hh];
__device__ float  g_wsum[Nn * Hh];
__device__ float  g_y1[Nn * OUT];
__device__ float  g_y2[Nn * OUT];
__device__ float  g_y3[Nn * OUT];
__device__ double g_stats[3 * 128];
__device__ float  g_pool[Bb * OUT];
__device__ float  g_cnt[Bb];

// ---------------- helpers ----------------
__device__ __forceinline__ void red_add_v4(float* addr, float4 v) {
    asm volatile("red.global.add.v4.f32 [%0], {%1,%2,%3,%4};"
                 :: "l"(addr), "f"(v.x), "f"(v.y), "f"(v.z), "f"(v.w) : "memory");
}

__device__ __forceinline__ void fma_row(float4& acc, float zv, float4 wv) {
    acc.x = fmaf(zv, wv.x, acc.x);
    acc.y = fmaf(zv, wv.y, acc.y);
    acc.z = fmaf(zv, wv.z, acc.z);
    acc.w = fmaf(zv, wv.w, acc.w);
}

// ---------------- 0: zero scratch ----------------
__global__ void zero_kernel() {
    int idx = blockIdx.x * blockDim.x + threadIdx.x;
    int stride = gridDim.x * blockDim.x;
    const int n4 = (Nn * Hh) / 4;
    float4 z4 = make_float4(0.f, 0.f, 0.f, 0.f);
    for (int i = idx; i < n4; i += stride) {
        reinterpret_cast<float4*>(g_esum)[i] = z4;
        reinterpret_cast<float4*>(g_wsum)[i] = z4;
    }
    for (int i = idx; i < Bb * OUT; i += stride) g_pool[i] = 0.f;
    for (int i = idx; i < Bb; i += stride) g_cnt[i] = 0.f;
    for (int i = idx; i < 3 * 128; i += stride) g_stats[i] = 0.0;
}

// ---------------- 1: node encoder  h = x @ node_w + node_b  [N,64]->[N,32] ----
__global__ void __launch_bounds__(256) enc_kernel(const float* __restrict__ x,
                                                  const float* __restrict__ W,
                                                  const float* __restrict__ bias) {
    __shared__ __align__(16) float zs[FIN * (TRE + 1)];
    __shared__ __align__(16) float ws[FIN * Hh];
    int tid = threadIdx.x;
    int n0 = blockIdx.x * TRE;
    for (int i = tid; i < (FIN * Hh) / 4; i += 256)
        reinterpret_cast<float4*>(ws)[i] = reinterpret_cast<const float4*>(W)[i];
    #pragma unroll
    for (int it = 0; it < 8; it++) {
        int idx = tid + it * 256;
        int row = idx >> 4, k4 = idx & 15;
        int gn = n0 + row;
        float4 v = make_float4(0.f, 0.f, 0.f, 0.f);
        if (gn < Nn) v = *reinterpret_cast<const float4*>(x + (size_t)gn * FIN + 4 * k4);
        zs[(4*k4+0) * (TRE+1) + row] = v.x;
        zs[(4*k4+1) * (TRE+1) + row] = v.y;
        zs[(4*k4+2) * (TRE+1) + row] = v.z;
        zs[(4*k4+3) * (TRE+1) + row] = v.w;
    }
    __syncthreads();
    int lane = tid & 31, w = tid >> 5;
    int cg = w & 1;
    int rq = w >> 1;
    int rl = 32 * rq + lane;
    float4 a0 = {0,0,0,0}, a1 = {0,0,0,0}, a2 = {0,0,0,0}, a3 = {0,0,0,0};
    const float4* ws4 = reinterpret_cast<const float4*>(ws);
    #pragma unroll 8
    for (int k = 0; k < FIN; k++) {
        float z = zs[k * (TRE+1) + rl];
        const float4* wr = ws4 + k * 8 + cg * 4;
        fma_row(a0, z, wr[0]); fma_row(a1, z, wr[1]);
        fma_row(a2, z, wr[2]); fma_row(a3, z, wr[3]);
    }
    int gn = n0 + rl;
    if (gn < Nn) {
        const float4* b4 = reinterpret_cast<const float4*>(bias) + cg * 4;
        float4 vv;
        float* op = g_h + (size_t)gn * Hh + 16 * cg;
        vv = a0; vv.x += b4[0].x; vv.y += b4[0].y; vv.z += b4[0].z; vv.w += b4[0].w;
        *reinterpret_cast<float4*>(op + 0) = vv;
        vv = a1; vv.x += b4[1].x; vv.y += b4[1].y; vv.z += b4[1].z; vv.w += b4[1].w;
        *reinterpret_cast<float4*>(op + 4) = vv;
        vv = a2; vv.x += b4[2].x; vv.y += b4[2].y; vv.z += b4[2].z; vv.w += b4[2].w;
        *reinterpret_cast<float4*>(op + 8) = vv;
        vv = a3; vv.x += b4[3].x; vv.y += b4[3].y; vv.z += b4[3].z; vv.w += b4[3].w;
        *reinterpret_cast<float4*>(op + 12) = vv;
    }
}

// ---------------- 2: edge pass (streamed, msg, exp, atomic segment sums) -------
__global__ void __launch_bounds__(256) edge_kernel(const int* __restrict__ ei,
                                                   const float* __restrict__ eattr,
                                                   const float* __restrict__ ew,
                                                   const float* __restrict__ eb) {
    __shared__ __align__(16) float sattr[32 * 20];
    __shared__ __align__(16) float sws[EIN * Hh];   // 16x32
    __shared__ int ssrc[32];
    __shared__ int sdst[32];
    int tid = threadIdx.x;
    for (int i = tid; i < EIN * Hh; i += 256) sws[i] = ew[i];
    int j = tid & 7;          // feature quad (feats 4j..4j+3)
    int el = tid >> 3;        // edge within tile (0..31)
    float4 eb4 = *reinterpret_cast<const float4*>(eb + 4*j);
    const float4* w4p = reinterpret_cast<const float4*>(sws); // [k][8]
    const int ntiles = Ee / 32;
    for (int t = blockIdx.x; t < ntiles; t += gridDim.x) {
        int e0 = t * 32;
        __syncthreads();
        {
            const float2* ap = reinterpret_cast<const float2*>(eattr + (size_t)e0 * EIN);
            float2 v = ap[tid];
            int row = tid >> 3, col = (tid & 7) * 2;
            sattr[row * 20 + col]     = v.x;
            sattr[row * 20 + col + 1] = v.y;
            if (tid < 32) ssrc[tid] = ei[e0 + tid];
            else if (tid < 64) sdst[tid - 32] = ei[Ee + e0 + (tid - 32)];
        }
        __syncthreads();
        int src = ssrc[el], dst = sdst[el];
        float4 ea = eb4;
        const float4* a4p = reinterpret_cast<const float4*>(sattr + el * 20);
        #pragma unroll
        for (int k4 = 0; k4 < 4; k4++) {
            float4 a4 = a4p[k4];
            float4 w0 = w4p[(4*k4+0)*8 + j];
            float4 w1 = w4p[(4*k4+1)*8 + j];
            float4 w2 = w4p[(4*k4+2)*8 + j];
            float4 w3 = w4p[(4*k4+3)*8 + j];
            fma_row(ea, a4.x, w0); fma_row(ea, a4.y, w1); fma_row(ea, a4.z, w2); fma_row(ea, a4.w, w3);
        }
        float4 hv = *reinterpret_cast<const float4*>(g_h + (size_t)src * Hh + 4*j);
        float4 m;
        m.x = fmaxf(hv.x + ea.x, 0.f) + EPS_GEN;
        m.y = fmaxf(hv.y + ea.y, 0.f) + EPS_GEN;
        m.z = fmaxf(hv.z + ea.z, 0.f) + EPS_GEN;
        m.w = fmaxf(hv.w + ea.w, 0.f) + EPS_GEN;
        float4 p;
        p.x = __expf(m.x); p.y = __expf(m.y); p.z = __expf(m.z); p.w = __expf(m.w);
        float* base_e = g_esum + (size_t)dst * Hh + 4*j;
        float* base_w = g_wsum + (size_t)dst * Hh + 4*j;
        red_add_v4(base_e, p);
        red_add_v4(base_w, make_float4(m.x*p.x, m.y*p.y, m.z*p.z, m.w*p.w));
    }
}

// ---------------- node-GEMM consumer: thread = 1 row x 16 cols ----------------
template<int K>
__device__ __forceinline__ void gemm16(const float* zs, const float* ws,
                                       const float* bias, float4 a[4],
                                       int& gn, int& cg, int n0, int tid) {
    int lane = tid & 31, w = tid >> 5;
    cg = w & 3;                 // cols 16*cg..16*cg+15
    int rh = w >> 2;            // row half (TR=64)
    int rl = 32 * rh + lane;
    a[0] = make_float4(0,0,0,0); a[1] = make_float4(0,0,0,0);
    a[2] = make_float4(0,0,0,0); a[3] = make_float4(0,0,0,0);
    const float4* ws4 = reinterpret_cast<const float4*>(ws);
    #pragma unroll 8
    for (int k = 0; k < K; k++) {
        float z = zs[k * (TR+1) + rl];
        const float4* wr = ws4 + k * 16 + cg * 4;
        fma_row(a[0], z, wr[0]); fma_row(a[1], z, wr[1]);
        fma_row(a[2], z, wr[2]); fma_row(a[3], z, wr[3]);
    }
    const float4* b4 = reinterpret_cast<const float4*>(bias) + cg * 4;
    #pragma unroll
    for (int i = 0; i < 4; i++) {
        float4 bb = b4[i];
        a[i].x += bb.x; a[i].y += bb.y; a[i].z += bb.z; a[i].w += bb.w;
    }
    gn = n0 + rl;
}

__device__ __forceinline__ void store_stats16(float4 a[4], int gn, int cg, int lane,
                                              float* out, float* ssum, float* ssq) {
    bool ok = gn < Nn;
    float* op = out + (size_t)gn * OUT + 16 * cg;
    #pragma unroll
    for (int i = 0; i < 4; i++) {
        if (ok) *reinterpret_cast<float4*>(op + 4*i) = a[i];
        else a[i] = make_float4(0,0,0,0);
    }
    #pragma unroll
    for (int i = 0; i < 4; i++) {
        int q = ((lane & 3) + i) & 3;
        float4 s = a[q];
        int c = 16 * cg + 4 * q;
        atomicAdd(&ssum[c+0], s.x); atomicAdd(&ssum[c+1], s.y);
        atomicAdd(&ssum[c+2], s.z); atomicAdd(&ssum[c+3], s.w);
        atomicAdd(&ssq[c+0], s.x*s.x); atomicAdd(&ssq[c+1], s.y*s.y);
        atomicAdd(&ssq[c+2], s.z*s.z); atomicAdd(&ssq[c+3], s.w*s.w);
    }
}

// ---------------- 3: stage A  z = agg + h ; y1 = z@W1+b1 ; stats1 -------------
__global__ void __launch_bounds__(256) stageA_kernel(const float* __restrict__ W,
                                                     const float* __restrict__ bias) {
    __shared__ __align__(16) float zs[Hh * (TR + 1)];
    __shared__ __align__(16) float ws[Hh * OUT];
    __shared__ float ssum[64], ssq[64];
    int tid = threadIdx.x;
    int n0 = blockIdx.x * TR;
    for (int i = tid; i < (Hh * OUT) / 4; i += 256)
        reinterpret_cast<float4*>(ws)[i] = reinterpret_cast<const float4*>(W)[i];
    if (tid < 64) { ssum[tid] = 0.f; ssq[tid] = 0.f; }
    // loader: 64 rows x 8 k4 = 512 float4
    #pragma unroll
    for (int it = 0; it < 2; it++) {
        int idx = tid + it * 256;
        int row = idx >> 3, k4 = idx & 7;
        int gn = n0 + row;
        float4 z = make_float4(0,0,0,0);
        if (gn < Nn) {
            float4 es = *reinterpret_cast<const float4*>(g_esum + (size_t)gn * Hh + 4*k4);
            float4 wsu = *reinterpret_cast<const float4*>(g_wsum + (size_t)gn * Hh + 4*k4);
            float4 hv = *reinterpret_cast<const float4*>(g_h + (size_t)gn * Hh + 4*k4);
            z.x = ((es.x > 0.f) ? wsu.x / es.x : 0.f) + hv.x;
            z.y = ((es.y > 0.f) ? wsu.y / es.y : 0.f) + hv.y;
            z.z = ((es.z > 0.f) ? wsu.z / es.z : 0.f) + hv.z;
            z.w = ((es.w > 0.f) ? wsu.w / es.w : 0.f) + hv.w;
        }
        zs[(4*k4+0) * (TR+1) + row] = z.x;
        zs[(4*k4+1) * (TR+1) + row] = z.y;
        zs[(4*k4+2) * (TR+1) + row] = z.z;
        zs[(4*k4+3) * (TR+1) + row] = z.w;
    }
    __syncthreads();
    float4 a[4]; int gn, cg;
    gemm16<Hh>(zs, ws, bias, a, gn, cg, n0, tid);
    store_stats16(a, gn, cg, tid & 31, g_y1, ssum, ssq);
    __syncthreads();
    if (tid < 64) {
        atomicAdd(&g_stats[tid],      (double)ssum[tid]);
        atomicAdd(&g_stats[64 + tid], (double)ssq[tid]);
    }
}

// ---------------- 4: stages B/C  z=relu(bn(in)) ; out=z@W+b ; stats ------------
__global__ void __launch_bounds__(256) stageBC_kernel(const float* __restrict__ W,
                                                      const float* __restrict__ bias,
                                                      const float* __restrict__ gam,
                                                      const float* __restrict__ bet,
                                                      int sel) {
    __shared__ __align__(16) float zs[OUT * (TR + 1)];
    __shared__ __align__(16) float ws[OUT * OUT];
    __shared__ float ssum[64], ssq[64], sscale[64], sshift[64];
    const float* in  = sel ? g_y2 : g_y1;
    float*       out = sel ? g_y3 : g_y2;
    int sin  = sel ? 128 : 0;
    int sout = sel ? 256 : 128;
    int tid = threadIdx.x;
    int n0 = blockIdx.x * TR;
    for (int i = tid; i < (OUT * OUT) / 4; i += 256)
        reinterpret_cast<float4*>(ws)[i] = reinterpret_cast<const float4*>(W)[i];
    if (tid < 64) {
        double mean = g_stats[sin + tid] / (double)Nn;
        double msq  = g_stats[sin + 64 + tid] / (double)Nn;
        double var  = msq - mean * mean;
        float sc = gam[tid] * rsqrtf((float)var + EPS_BN);
        sscale[tid] = sc;
        sshift[tid] = bet[tid] - (float)mean * sc;
        ssum[tid] = 0.f; ssq[tid] = 0.f;
    }
    __syncthreads();
    // loader: 64 rows x 16 k4 = 1024 float4
    #pragma unroll
    for (int it = 0; it < 4; it++) {
        int idx = tid + it * 256;
        int row = idx >> 4, k4 = idx & 15;
        int gn = n0 + row;
        float4 v = make_float4(0,0,0,0);
        if (gn < Nn) v = *reinterpret_cast<const float4*>(in + (size_t)gn * OUT + 4*k4);
        zs[(4*k4+0) * (TR+1) + row] = fmaxf(sscale[4*k4+0] * v.x + sshift[4*k4+0], 0.f);
        zs[(4*k4+1) * (TR+1) + row] = fmaxf(sscale[4*k4+1] * v.y + sshift[4*k4+1], 0.f);
        zs[(4*k4+2) * (TR+1) + row] = fmaxf(sscale[4*k4+2] * v.z + sshift[4*k4+2], 0.f);
        zs[(4*k4+3) * (TR+1) + row] = fmaxf(sscale[4*k4+3] * v.w + sshift[4*k4+3], 0.f);
    }
    __syncthreads();
    float4 a[4]; int gn, cg;
    gemm16<OUT>(zs, ws, bias, a, gn, cg, n0, tid);
    store_stats16(a, gn, cg, tid & 31, out, ssum, ssq);
    __syncthreads();
    if (tid < 64) {
        atomicAdd(&g_stats[sout + tid],      (double)ssum[tid]);
        atomicAdd(&g_stats[sout + 64 + tid], (double)ssq[tid]);
    }
}

// ---------------- 5: stage D  node_out = relu(bn3(y3))@W4+b4, pooled -----------
__global__ void __launch_bounds__(256) stageD_kernel(const float* __restrict__ W,
                                                     const float* __restrict__ bias,
                                                     const float* __restrict__ gam,
                                                     const float* __restrict__ bet,
                                                     const int* __restrict__ batch) {
    __shared__ __align__(16) float zs[OUT * (TR + 1)];
    __shared__ __align__(16) float ws[OUT * OUT];
    __shared__ float sscale[64], sshift[64];
    int tid = threadIdx.x;
    int n0 = blockIdx.x * TR;
    for (int i = tid; i < (OUT * OUT) / 4; i += 256)
        reinterpret_cast<float4*>(ws)[i] = reinterpret_cast<const float4*>(W)[i];
    if (tid < 64) {
        double mean = g_stats[256 + tid] / (double)Nn;
        double msq  = g_stats[256 + 64 + tid] / (double)Nn;
        double var  = msq - mean * mean;
        float sc = gam[tid] * rsqrtf((float)var + EPS_BN);
        sscale[tid] = sc;
        sshift[tid] = bet[tid] - (float)mean * sc;
    }
    __syncthreads();
    #pragma unroll
    for (int it = 0; it < 4; it++) {
        int idx = tid + it * 256;
        int row = idx >> 4, k4 = idx & 15;
        int gn = n0 + row;
        float4 v = make_float4(0,0,0,0);
        if (gn < Nn) v = *reinterpret_cast<const float4*>(g_y3 + (size_t)gn * OUT + 4*k4);
        zs[(4*k4+0) * (TR+1) + row] = fmaxf(sscale[4*k4+0] * v.x + sshift[4*k4+0], 0.f);
        zs[(4*k4+1) * (TR+1) + row] = fmaxf(sscale[4*k4+1] * v.y + sshift[4*k4+1], 0.f);
        zs[(4*k4+2) * (TR+1) + row] = fmaxf(sscale[4*k4+2] * v.z + sshift[4*k4+2], 0.f);
        zs[(4*k4+3) * (TR+1) + row] = fmaxf(sscale[4*k4+3] * v.w + sshift[4*k4+3], 0.f);
    }
    __syncthreads();
    float4 a[4]; int gn, cg;
    gemm16<OUT>(zs, ws, bias, a, gn, cg, n0, tid);
    if (gn < Nn) {
        int g = batch[gn];
        float* pp = g_pool + (size_t)g * OUT + 16 * cg;
        #pragma unroll
        for (int i = 0; i < 4; i++) red_add_v4(pp + 4*i, a[i]);
        if (cg == 0) atomicAdd(&g_cnt[g], 1.0f);
    }
}

// ---------------- 6: head (per graph) -----------------------------------------
__global__ void head_kernel(const float* __restrict__ action,
                            const float* __restrict__ pinw, const float* __restrict__ pinb,
                            const float* __restrict__ phw,  const float* __restrict__ phb,
                            const float* __restrict__ pow_, const float* __restrict__ pob,
                            float* __restrict__ outp) {
    int g = threadIdx.x;
    if (g >= Bb) return;
    float inv = 1.0f / fmaxf(g_cnt[g], 1.0f);
    float fp[16];
    #pragma unroll
    for (int jj = 0; jj < 16; jj++) {
        float s = 0.f;
        for (int f = 0; f < OUT; f++) s += g_pool[g * OUT + f] * pinw[f * 16 + jj];
        fp[jj] = fmaxf(s * inv + pinb[jj], 0.f);
    }
    float res = pob[0];
    #pragma unroll
    for (int q = 0; q < 10; q++) {
        float s = phb[q];
        #pragma unroll
        for (int jj = 0; jj < 16; jj++) s += fp[jj] * phw[jj * 10 + q];
        #pragma unroll
        for (int a = 0; a < ADIM; a++) s += action[g * ADIM + a] * phw[(16 + a) * 10 + q];
        res += fmaxf(s, 0.f) * pow_[q];
    }
    outp[g] = res;
}

// ---------------- launch -------------------------------------------------------
extern "C" void kernel_launch(void* const* d_in, const int* in_sizes, int n_in,
                              void* d_out, int out_size) {
    const float* x      = (const float*)d_in[0];
    const int*   ei     = (const int*)  d_in[1];
    const float* eattr  = (const float*)d_in[2];
    const int*   batch  = (const int*)  d_in[3];
    const float* action = (const float*)d_in[4];
    const float* node_w = (const float*)d_in[5];
    const float* node_b = (const float*)d_in[6];
    const float* edge_w = (const float*)d_in[7];
    const float* edge_b = (const float*)d_in[8];
    const float* w1 = (const float*)d_in[9];  const float* b1 = (const float*)d_in[10];
    const float* g1 = (const float*)d_in[11]; const float* bb1 = (const float*)d_in[12];
    const float* w2 = (const float*)d_in[13]; const float* b2 = (const float*)d_in[14];
    const float* g2 = (const float*)d_in[15]; const float* bb2 = (const float*)d_in[16];
    const float* w3 = (const float*)d_in[17]; const float* b3 = (const float*)d_in[18];
    const float* g3 = (const float*)d_in[19]; const float* bb3 = (const float*)d_in[20];
    const float* w4 = (const float*)d_in[21]; const float* b4 = (const float*)d_in[22];
    const float* pinw = (const float*)d_in[23]; const float* pinb = (const float*)d_in[24];
    const float* phw  = (const float*)d_in[25]; const float* phb  = (const float*)d_in[26];
    const float* pow_ = (const float*)d_in[27]; const float* pob  = (const float*)d_in[28];

    zero_kernel<<<2048, 256>>>();
    enc_kernel<<<NBLK128, 256>>>(x, node_w, node_b);
    edge_kernel<<<2048, 256>>>(ei, eattr, edge_w, edge_b);
    stageA_kernel<<<NBLK64, 256>>>(w1, b1);
    stageBC_kernel<<<NBLK64, 256>>>(w2, b2, g1, bb1, 0);
    stageBC_kernel<<<NBLK64, 256>>>(w3, b3, g2, bb2, 1);
    stageD_kernel<<<NBLK64, 256>>>(w4, b4, g3, bb3, batch);
    head_kernel<<<1, 64>>>(action, pinw, pinb, phw, phb, pow_, pob, (float*)d_out);
}

// round 12
// speedup vs baseline: 1.3015x; 1.1294x over previous
#include <cuda_runtime.h>
#include <cuda_bf16.h>
#include <cstdint>

#define Nn 100000
#define Ee 3200000
#define Bb 64
#define FIN 64
#define EIN 16
#define ADIM 13
#define Hh 32
#define OUT 64
#define EPS_GEN 1e-7f
#define EPS_BN 1e-5f

// ---------------- scratch (device globals; no allocs allowed) ----------------
__device__ float  g_h[Nn * Hh];        // node encoder output [N,32]
__device__ float  g_esum[Nn * Hh];     // sum of exp(msg) per dst
__device__ float  g_wsum[Nn * Hh];     // sum of msg*exp(msg) per dst
__device__ float  g_y1[Nn * OUT];
__device__ float  g_y2[Nn * OUT];
__device__ float  g_y3[Nn * OUT];
__device__ double g_stats[3 * 128];    // per stage: [sum(64) | sumsq(64)]
__device__ float  g_pool[Bb * OUT];
__device__ float  g_cnt[Bb];

// ---------------- helpers ----------------
__device__ __forceinline__ void red_add_v4(float* addr, float4 v) {
    asm volatile("red.global.add.v4.f32 [%0], {%1,%2,%3,%4};"
                 :: "l"(addr), "f"(v.x), "f"(v.y), "f"(v.z), "f"(v.w) : "memory");
}

__device__ __forceinline__ void fma_row(float4& acc, float zv, float4 wv) {
    acc.x = fmaf(zv, wv.x, acc.x);
    acc.y = fmaf(zv, wv.y, acc.y);
    acc.z = fmaf(zv, wv.z, acc.z);
    acc.w = fmaf(zv, wv.w, acc.w);
}

// ---------------- noop (launch-order shim so ncu profiles edge_kernel) --------
__global__ void noop_kernel() {}

// ---------------- 0: zero scratch ----------------
__global__ void zero_kernel() {
    int idx = blockIdx.x * blockDim.x + threadIdx.x;
    int stride = gridDim.x * blockDim.x;
    const int n4 = (Nn * Hh) / 4;
    float4 z4 = make_float4(0.f, 0.f, 0.f, 0.f);
    for (int i = idx; i < n4; i += stride) {
        reinterpret_cast<float4*>(g_esum)[i] = z4;
        reinterpret_cast<float4*>(g_wsum)[i] = z4;
    }
    for (int i = idx; i < Bb * OUT; i += stride) g_pool[i] = 0.f;
    for (int i = idx; i < Bb; i += stride) g_cnt[i] = 0.f;
    for (int i = idx; i < 3 * 128; i += stride) g_stats[i] = 0.0;
}

// ---------------- 1: node encoder  h = x @ node_w + node_b  [N,64]->[N,32] ----
__global__ void __launch_bounds__(128) enc_kernel(const float* __restrict__ x,
                                                  const float* __restrict__ W,
                                                  const float* __restrict__ bias) {
    __shared__ __align__(16) float zs[64 * 68];
    __shared__ __align__(16) float ws[FIN * Hh];   // 64x32
    int tid = threadIdx.x;
    int n0 = blockIdx.x * 64;
    for (int i = tid; i < FIN * Hh; i += 128) ws[i] = W[i];
    for (int i = tid; i < 64 * FIN; i += 128) {
        int n = i >> 6, k = i & 63;
        int gn = n0 + n;
        zs[n * 68 + k] = (gn < Nn) ? x[(size_t)gn * FIN + k] : 0.f;
    }
    __syncthreads();
    int ti = tid >> 3, tj = tid & 7;           // 16 x 8
    float4 acc0 = {0,0,0,0}, acc1 = {0,0,0,0}, acc2 = {0,0,0,0}, acc3 = {0,0,0,0};
    const float4* ws4 = reinterpret_cast<const float4*>(ws); // [k][8]
    #pragma unroll
    for (int k4 = 0; k4 < 16; k4++) {
        float4 z0 = *reinterpret_cast<const float4*>(zs + (4*ti+0)*68 + 4*k4);
        float4 z1 = *reinterpret_cast<const float4*>(zs + (4*ti+1)*68 + 4*k4);
        float4 z2 = *reinterpret_cast<const float4*>(zs + (4*ti+2)*68 + 4*k4);
        float4 z3 = *reinterpret_cast<const float4*>(zs + (4*ti+3)*68 + 4*k4);
        float4 w0 = ws4[(4*k4+0)*8 + tj];
        float4 w1 = ws4[(4*k4+1)*8 + tj];
        float4 w2 = ws4[(4*k4+2)*8 + tj];
        float4 w3 = ws4[(4*k4+3)*8 + tj];
        fma_row(acc0, z0.x, w0); fma_row(acc0, z0.y, w1); fma_row(acc0, z0.z, w2); fma_row(acc0, z0.w, w3);
        fma_row(acc1, z1.x, w0); fma_row(acc1, z1.y, w1); fma_row(acc1, z1.z, w2); fma_row(acc1, z1.w, w3);
        fma_row(acc2, z2.x, w0); fma_row(acc2, z2.y, w1); fma_row(acc2, z2.z, w2); fma_row(acc2, z2.w, w3);
        fma_row(acc3, z3.x, w0); fma_row(acc3, z3.y, w1); fma_row(acc3, z3.z, w2); fma_row(acc3, z3.w, w3);
    }
    float4 bb = *reinterpret_cast<const float4*>(bias + 4*tj);
    float4 accs[4] = {acc0, acc1, acc2, acc3};
    #pragma unroll
    for (int r = 0; r < 4; r++) {
        int gn = n0 + 4*ti + r;
        if (gn < Nn) {
            float4 v = accs[r];
            v.x += bb.x; v.y += bb.y; v.z += bb.z; v.w += bb.w;
            *reinterpret_cast<float4*>(g_h + (size_t)gn * Hh + 4*tj) = v;
        }
    }
}

// ---------------- 2: edge pass (streamed, 64 edges/tile) ----------------------
__global__ void __launch_bounds__(256) edge_kernel(const int* __restrict__ ei,
                                                   const float* __restrict__ eattr,
                                                   const float* __restrict__ ew,
                                                   const float* __restrict__ eb) {
    __shared__ __align__(16) float sattr[64 * 20];
    __shared__ __align__(16) float sws[EIN * Hh];   // 16x32
    __shared__ int ssrc[64];
    __shared__ int sdst[64];
    int tid = threadIdx.x;
    for (int i = tid; i < EIN * Hh; i += 256) sws[i] = ew[i];
    int j = tid & 7;          // feature quad (feats 4j..4j+3)
    int el = tid >> 3;        // edge within half-tile (0..31)
    float4 eb4 = *reinterpret_cast<const float4*>(eb + 4*j);
    const float4* w4p = reinterpret_cast<const float4*>(sws); // [k][8]
    const int ntiles = Ee / 64;
    for (int t = blockIdx.x; t < ntiles; t += gridDim.x) {
        int e0 = t * 64;
        __syncthreads();
        {
            const float2* ap = reinterpret_cast<const float2*>(eattr + (size_t)e0 * EIN);
            #pragma unroll
            for (int it = 0; it < 2; it++) {
                int idx = tid + it * 256;
                float2 v = ap[idx];
                int row = idx >> 3, col = (idx & 7) * 2;
                sattr[row * 20 + col]     = v.x;
                sattr[row * 20 + col + 1] = v.y;
            }
            if (tid < 64) ssrc[tid] = ei[e0 + tid];
            else if (tid < 128) sdst[tid - 64] = ei[Ee + e0 + (tid - 64)];
        }
        __syncthreads();
        #pragma unroll
        for (int sub = 0; sub < 2; sub++) {
            int ee = el + 32 * sub;
            int src = ssrc[ee], dst = sdst[ee];
            float4 ea = eb4;
            const float4* a4p = reinterpret_cast<const float4*>(sattr + ee * 20);
            #pragma unroll
            for (int k4 = 0; k4 < 4; k4++) {
                float4 a4 = a4p[k4];
                float4 w0 = w4p[(4*k4+0)*8 + j];
                float4 w1 = w4p[(4*k4+1)*8 + j];
                float4 w2 = w4p[(4*k4+2)*8 + j];
                float4 w3 = w4p[(4*k4+3)*8 + j];
                fma_row(ea, a4.x, w0); fma_row(ea, a4.y, w1); fma_row(ea, a4.z, w2); fma_row(ea, a4.w, w3);
            }
            float4 hv = *reinterpret_cast<const float4*>(g_h + (size_t)src * Hh + 4*j);
            float4 m;
            m.x = fmaxf(hv.x + ea.x, 0.f) + EPS_GEN;
            m.y = fmaxf(hv.y + ea.y, 0.f) + EPS_GEN;
            m.z = fmaxf(hv.z + ea.z, 0.f) + EPS_GEN;
            m.w = fmaxf(hv.w + ea.w, 0.f) + EPS_GEN;
            float4 p;
            p.x = __expf(m.x); p.y = __expf(m.y); p.z = __expf(m.z); p.w = __expf(m.w);
            red_add_v4(g_esum + (size_t)dst * Hh + 4*j, p);
            red_add_v4(g_wsum + (size_t)dst * Hh + 4*j,
                       make_float4(m.x*p.x, m.y*p.y, m.z*p.z, m.w*p.w));
        }
    }
}

// ---------------- 3: stage A  out32 = agg + h ; y1 = out32@W1+b1 ; stats1 ------
__global__ void __launch_bounds__(256) stageA_kernel(const float* __restrict__ W,
                                                     const float* __restrict__ bias) {
    __shared__ __align__(16) float zs[64 * 36];
    __shared__ __align__(16) float ws[Hh * OUT];   // 32x64
    __shared__ float ssum[64], ssq[64];
    int tid = threadIdx.x;
    int n0 = blockIdx.x * 64;
    for (int i = tid; i < Hh * OUT; i += 256) ws[i] = W[i];
    if (tid < 64) { ssum[tid] = 0.f; ssq[tid] = 0.f; }
    for (int i = tid; i < 64 * Hh; i += 256) {
        int n = i >> 5, k = i & 31;
        int gn = n0 + n;
        float z = 0.f;
        if (gn < Nn) {
            float es = g_esum[(size_t)gn * Hh + k];
            float agg = (es > 0.f) ? g_wsum[(size_t)gn * Hh + k] / es : 0.f;
            z = agg + g_h[(size_t)gn * Hh + k];
        }
        zs[n * 36 + k] = z;
    }
    __syncthreads();
    int ti = tid >> 4, tj = tid & 15;
    float4 acc0 = {0,0,0,0}, acc1 = {0,0,0,0}, acc2 = {0,0,0,0}, acc3 = {0,0,0,0};
    const float4* ws4 = reinterpret_cast<const float4*>(ws); // [k][16]
    #pragma unroll
    for (int k4 = 0; k4 < 8; k4++) {
        float4 z0 = *reinterpret_cast<const float4*>(zs + (4*ti+0)*36 + 4*k4);
        float4 z1 = *reinterpret_cast<const float4*>(zs + (4*ti+1)*36 + 4*k4);
        float4 z2 = *reinterpret_cast<const float4*>(zs + (4*ti+2)*36 + 4*k4);
        float4 z3 = *reinterpret_cast<const float4*>(zs + (4*ti+3)*36 + 4*k4);
        float4 w0 = ws4[(4*k4+0)*16 + tj];
        float4 w1 = ws4[(4*k4+1)*16 + tj];
        float4 w2 = ws4[(4*k4+2)*16 + tj];
        float4 w3 = ws4[(4*k4+3)*16 + tj];
        fma_row(acc0, z0.x, w0); fma_row(acc0, z0.y, w1); fma_row(acc0, z0.z, w2); fma_row(acc0, z0.w, w3);
        fma_row(acc1, z1.x, w0); fma_row(acc1, z1.y, w1); fma_row(acc1, z1.z, w2); fma_row(acc1, z1.w, w3);
        fma_row(acc2, z2.x, w0); fma_row(acc2, z2.y, w1); fma_row(acc2, z2.z, w2); fma_row(acc2, z2.w, w3);
        fma_row(acc3, z3.x, w0); fma_row(acc3, z3.y, w1); fma_row(acc3, z3.z, w2); fma_row(acc3, z3.w, w3);
    }
    float4 bb = *reinterpret_cast<const float4*>(bias + 4*tj);
    float4 accs[4] = {acc0, acc1, acc2, acc3};
    float4 ls = {0,0,0,0}, lq = {0,0,0,0};
    #pragma unroll
    for (int r = 0; r < 4; r++) {
        int gn = n0 + 4*ti + r;
        if (gn < Nn) {
            float4 v = accs[r];
            v.x += bb.x; v.y += bb.y; v.z += bb.z; v.w += bb.w;
            *reinterpret_cast<float4*>(g_y1 + (size_t)gn * OUT + 4*tj) = v;
            ls.x += v.x; ls.y += v.y; ls.z += v.z; ls.w += v.w;
            lq.x += v.x*v.x; lq.y += v.y*v.y; lq.z += v.z*v.z; lq.w += v.w*v.w;
        }
    }
    atomicAdd(&ssum[4*tj+0], ls.x); atomicAdd(&ssum[4*tj+1], ls.y);
    atomicAdd(&ssum[4*tj+2], ls.z); atomicAdd(&ssum[4*tj+3], ls.w);
    atomicAdd(&ssq[4*tj+0], lq.x);  atomicAdd(&ssq[4*tj+1], lq.y);
    atomicAdd(&ssq[4*tj+2], lq.z);  atomicAdd(&ssq[4*tj+3], lq.w);
    __syncthreads();
    if (tid < 64) {
        atomicAdd(&g_stats[tid],      (double)ssum[tid]);
        atomicAdd(&g_stats[64 + tid], (double)ssq[tid]);
    }
}

// ---------------- 4: stages B/C  z=relu(bn(in)) ; out=z@W+b ; stats ------------
__global__ void __launch_bounds__(256) stageBC_kernel(const float* __restrict__ W,
                                                      const float* __restrict__ bias,
                                                      const float* __restrict__ gam,
                                                      const float* __restrict__ bet,
                                                      int sel) {
    __shared__ __align__(16) float zs[64 * 68];
    __shared__ __align__(16) float ws[OUT * OUT];  // 64x64
    __shared__ float ssum[64], ssq[64], sscale[64], sshift[64];
    const float* in  = sel ? g_y2 : g_y1;
    float*       out = sel ? g_y3 : g_y2;
    int sin  = sel ? 128 : 0;
    int sout = sel ? 256 : 128;
    int tid = threadIdx.x;
    int n0 = blockIdx.x * 64;
    for (int i = tid; i < OUT * OUT; i += 256) ws[i] = W[i];
    if (tid < 64) {
        double mean = g_stats[sin + tid] / (double)Nn;
        double msq  = g_stats[sin + 64 + tid] / (double)Nn;
        double var  = msq - mean * mean;
        float sc = gam[tid] * rsqrtf((float)var + EPS_BN);
        sscale[tid] = sc;
        sshift[tid] = bet[tid] - (float)mean * sc;
        ssum[tid] = 0.f; ssq[tid] = 0.f;
    }
    __syncthreads();
    for (int i = tid; i < 64 * OUT; i += 256) {
        int n = i >> 6, k = i & 63;
        int gn = n0 + n;
        float z = 0.f;
        if (gn < Nn) z = fmaxf(sscale[k] * in[(size_t)gn * OUT + k] + sshift[k], 0.f);
        zs[n * 68 + k] = z;
    }
    __syncthreads();
    int ti = tid >> 4, tj = tid & 15;
    float4 acc0 = {0,0,0,0}, acc1 = {0,0,0,0}, acc2 = {0,0,0,0}, acc3 = {0,0,0,0};
    const float4* ws4 = reinterpret_cast<const float4*>(ws);
    #pragma unroll
    for (int k4 = 0; k4 < 16; k4++) {
        float4 z0 = *reinterpret_cast<const float4*>(zs + (4*ti+0)*68 + 4*k4);
        float4 z1 = *reinterpret_cast<const float4*>(zs + (4*ti+1)*68 + 4*k4);
        float4 z2 = *reinterpret_cast<const float4*>(zs + (4*ti+2)*68 + 4*k4);
        float4 z3 = *reinterpret_cast<const float4*>(zs + (4*ti+3)*68 + 4*k4);
        float4 w0 = ws4[(4*k4+0)*16 + tj];
        float4 w1 = ws4[(4*k4+1)*16 + tj];
        float4 w2 = ws4[(4*k4+2)*16 + tj];
        float4 w3 = ws4[(4*k4+3)*16 + tj];
        fma_row(acc0, z0.x, w0); fma_row(acc0, z0.y, w1); fma_row(acc0, z0.z, w2); fma_row(acc0, z0.w, w3);
        fma_row(acc1, z1.x, w0); fma_row(acc1, z1.y, w1); fma_row(acc1, z1.z, w2); fma_row(acc1, z1.w, w3);
        fma_row(acc2, z2.x, w0); fma_row(acc2, z2.y, w1); fma_row(acc2, z2.z, w2); fma_row(acc2, z2.w, w3);
        fma_row(acc3, z3.x, w0); fma_row(acc3, z3.y, w1); fma_row(acc3, z3.z, w2); fma_row(acc3, z3.w, w3);
    }
    float4 bb = *reinterpret_cast<const float4*>(bias + 4*tj);
    float4 accs[4] = {acc0, acc1, acc2, acc3};
    float4 ls = {0,0,0,0}, lq = {0,0,0,0};
    #pragma unroll
    for (int r = 0; r < 4; r++) {
        int gn = n0 + 4*ti + r;
        if (gn < Nn) {
            float4 v = accs[r];
            v.x += bb.x; v.y += bb.y; v.z += bb.z; v.w += bb.w;
            *reinterpret_cast<float4*>(out + (size_t)gn * OUT + 4*tj) = v;
            ls.x += v.x; ls.y += v.y; ls.z += v.z; ls.w += v.w;
            lq.x += v.x*v.x; lq.y += v.y*v.y; lq.z += v.z*v.z; lq.w += v.w*v.w;
        }
    }
    atomicAdd(&ssum[4*tj+0], ls.x); atomicAdd(&ssum[4*tj+1], ls.y);
    atomicAdd(&ssum[4*tj+2], ls.z); atomicAdd(&ssum[4*tj+3], ls.w);
    atomicAdd(&ssq[4*tj+0], lq.x);  atomicAdd(&ssq[4*tj+1], lq.y);
    atomicAdd(&ssq[4*tj+2], lq.z);  atomicAdd(&ssq[4*tj+3], lq.w);
    __syncthreads();
    if (tid < 64) {
        atomicAdd(&g_stats[sout + tid],      (double)ssum[tid]);
        atomicAdd(&g_stats[sout + 64 + tid], (double)ssq[tid]);
    }
}

// ---------------- 5: stage D  node_out = relu(bn3(y3))@W4+b4, pooled -----------
__global__ void __launch_bounds__(256) stageD_kernel(const float* __restrict__ W,
                                                     const float* __restrict__ bias,
                                                     const float* __restrict__ gam,
                                                     const float* __restrict__ bet,
                                                     const int* __restrict__ batch) {
    __shared__ __align__(16) float zs[64 * 68];
    __shared__ __align__(16) float ws[OUT * OUT];
    __shared__ float sscale[64], sshift[64];
    int tid = threadIdx.x;
    int n0 = blockIdx.x * 64;
    for (int i = tid; i < OUT * OUT; i += 256) ws[i] = W[i];
    if (tid < 64) {
        double mean = g_stats[256 + tid] / (double)Nn;
        double msq  = g_stats[256 + 64 + tid] / (double)Nn;
        double var  = msq - mean * mean;
        float sc = gam[tid] * rsqrtf((float)var + EPS_BN);
        sscale[tid] = sc;
        sshift[tid] = bet[tid] - (float)mean * sc;
    }
    __syncthreads();
    for (int i = tid; i < 64 * OUT; i += 256) {
        int n = i >> 6, k = i & 63;
        int gn = n0 + n;
        float z = 0.f;
        if (gn < Nn) z = fmaxf(sscale[k] * g_y3[(size_t)gn * OUT + k] + sshift[k], 0.f);
        zs[n * 68 + k] = z;
    }
    __syncthreads();
    int ti = tid >> 4, tj = tid & 15;
    float4 acc0 = {0,0,0,0}, acc1 = {0,0,0,0}, acc2 = {0,0,0,0}, acc3 = {0,0,0,0};
    const float4* ws4 = reinterpret_cast<const float4*>(ws);
    #pragma unroll
    for (int k4 = 0; k4 < 16; k4++) {
        float4 z0 = *reinterpret_cast<const float4*>(zs + (4*ti+0)*68 + 4*k4);
        float4 z1 = *reinterpret_cast<const float4*>(zs + (4*ti+1)*68 + 4*k4);
        float4 z2 = *reinterpret_cast<const float4*>(zs + (4*ti+2)*68 + 4*k4);
        float4 z3 = *reinterpret_cast<const float4*>(zs + (4*ti+3)*68 + 4*k4);
        float4 w0 = ws4[(4*k4+0)*16 + tj];
        float4 w1 = ws4[(4*k4+1)*16 + tj];
        float4 w2 = ws4[(4*k4+2)*16 + tj];
        float4 w3 = ws4[(4*k4+3)*16 + tj];
        fma_row(acc0, z0.x, w0); fma_row(acc0, z0.y, w1); fma_row(acc0, z0.z, w2); fma_row(acc0, z0.w, w3);
        fma_row(acc1, z1.x, w0); fma_row(acc1, z1.y, w1); fma_row(acc1, z1.z, w2); fma_row(acc1, z1.w, w3);
        fma_row(acc2, z2.x, w0); fma_row(acc2, z2.y, w1); fma_row(acc2, z2.z, w2); fma_row(acc2, z2.w, w3);
        fma_row(acc3, z3.x, w0); fma_row(acc3, z3.y, w1); fma_row(acc3, z3.z, w2); fma_row(acc3, z3.w, w3);
    }
    float4 bb = *reinterpret_cast<const float4*>(bias + 4*tj);
    float4 accs[4] = {acc0, acc1, acc2, acc3};
    #pragma unroll
    for (int r = 0; r < 4; r++) {
        int gn = n0 + 4*ti + r;
        if (gn < Nn) {
            float4 v = accs[r];
            v.x += bb.x; v.y += bb.y; v.z += bb.z; v.w += bb.w;
            int g = batch[gn];
            red_add_v4(&g_pool[(size_t)g * OUT + 4*tj], v);
            if (tj == 0) atomicAdd(&g_cnt[g], 1.0f);
        }
    }
}

// ---------------- 6: head (per graph) -----------------------------------------
__global__ void head_kernel(const float* __restrict__ action,
                            const float* __restrict__ pinw, const float* __restrict__ pinb,
                            const float* __restrict__ phw,  const float* __restrict__ phb,
                            const float* __restrict__ pow_, const float* __restrict__ pob,
                            float* __restrict__ outp) {
    int g = threadIdx.x;
    if (g >= Bb) return;
    float inv = 1.0f / fmaxf(g_cnt[g], 1.0f);
    float fp[16];
    #pragma unroll
    for (int jj = 0; jj < 16; jj++) {
        float s = 0.f;
        for (int f = 0; f < OUT; f++) s += g_pool[g * OUT + f] * pinw[f * 16 + jj];
        fp[jj] = fmaxf(s * inv + pinb[jj], 0.f);
    }
    float res = pob[0];
    #pragma unroll
    for (int q = 0; q < 10; q++) {
        float s = phb[q];
        #pragma unroll
        for (int jj = 0; jj < 16; jj++) s += fp[jj] * phw[jj * 10 + q];
        #pragma unroll
        for (int a = 0; a < ADIM; a++) s += action[g * ADIM + a] * phw[(16 + a) * 10 + q];
        res += fmaxf(s, 0.f) * pow_[q];
    }
    outp[g] = res;
}

// ---------------- launch -------------------------------------------------------
extern "C" void kernel_launch(void* const* d_in, const int* in_sizes, int n_in,
                              void* d_out, int out_size) {
    const float* x      = (const float*)d_in[0];
    const int*   ei     = (const int*)  d_in[1];
    const float* eattr  = (const float*)d_in[2];
    const int*   batch  = (const int*)  d_in[3];
    const float* action = (const float*)d_in[4];
    const float* node_w = (const float*)d_in[5];
    const float* node_b = (const float*)d_in[6];
    const float* edge_w = (const float*)d_in[7];
    const float* edge_b = (const float*)d_in[8];
    const float* w1 = (const float*)d_in[9];  const float* b1 = (const float*)d_in[10];
    const float* g1 = (const float*)d_in[11]; const float* bb1 = (const float*)d_in[12];
    const float* w2 = (const float*)d_in[13]; const float* b2 = (const float*)d_in[14];
    const float* g2 = (const float*)d_in[15]; const float* bb2 = (const float*)d_in[16];
    const float* w3 = (const float*)d_in[17]; const float* b3 = (const float*)d_in[18];
    const float* g3 = (const float*)d_in[19]; const float* bb3 = (const float*)d_in[20];
    const float* w4 = (const float*)d_in[21]; const float* b4 = (const float*)d_in[22];
    const float* pinw = (const float*)d_in[23]; const float* pinb = (const float*)d_in[24];
    const float* phw  = (const float*)d_in[25]; const float* phb  = (const float*)d_in[26];
    const float* pow_ = (const float*)d_in[27]; const float* pob  = (const float*)d_in[28];

    const int NBLK = (Nn + 63) / 64;  // 1563

    zero_kernel<<<2048, 256>>>();                       // 1
    enc_kernel<<<NBLK, 128>>>(x, node_w, node_b);       // 2
    noop_kernel<<<1, 32>>>();                           // 3 (shifts edge to profiled slot)
    edge_kernel<<<2048, 256>>>(ei, eattr, edge_w, edge_b); // 4 <- ncu captures this
    stageA_kernel<<<NBLK, 256>>>(w1, b1);
    stageBC_kernel<<<NBLK, 256>>>(w2, b2, g1, bb1, 0);
    stageBC_kernel<<<NBLK, 256>>>(w3, b3, g2, bb2, 1);
    stageD_kernel<<<NBLK, 256>>>(w4, b4, g3, bb3, batch);
    head_kernel<<<1, 64>>>(action, pinw, pinb, phw, phb, pow_, pob, (float*)d_out);
}

// round 13
// speedup vs baseline: 1.3150x; 1.0104x over previous
#include <cuda_runtime.h>
#include <cuda_bf16.h>
#include <cstdint>

#define Nn 100000
#define Ee 3200000
#define Bb 64
#define FIN 64
#define EIN 16
#define ADIM 13
#define Hh 32
#define OUT 64
#define EPS_GEN 1e-7f
#define EPS_BN 1e-5f

// ---------------- scratch (device globals; no allocs allowed) ----------------
__device__ float  g_h[Nn * Hh];        // node encoder output [N,32]
__device__ float  g_esum[Nn * Hh];     // sum of exp(msg) per dst
__device__ float  g_wsum[Nn * Hh];     // sum of msg*exp(msg) per dst
__device__ float  g_y1[Nn * OUT];
__device__ float  g_y2[Nn * OUT];
__device__ float  g_y3[Nn * OUT];
__device__ double g_stats[3 * 128];    // per stage: [sum(64) | sumsq(64)]
__device__ float  g_pool[Bb * OUT];
__device__ float  g_cnt[Bb];

// ---------------- helpers ----------------
__device__ __forceinline__ void red_add_v4(float* addr, float4 v) {
    asm volatile("red.global.add.v4.f32 [%0], {%1,%2,%3,%4};"
                 :: "l"(addr), "f"(v.x), "f"(v.y), "f"(v.z), "f"(v.w) : "memory");
}

__device__ __forceinline__ void fma_row(float4& acc, float zv, float4 wv) {
    acc.x = fmaf(zv, wv.x, acc.x);
    acc.y = fmaf(zv, wv.y, acc.y);
    acc.z = fmaf(zv, wv.z, acc.z);
    acc.w = fmaf(zv, wv.w, acc.w);
}

// ---------------- noop (launch-order shim so ncu profiles edge_kernel) --------
__global__ void noop_kernel() {}

// ---------------- 0: zero scratch ----------------
__global__ void zero_kernel() {
    int idx = blockIdx.x * blockDim.x + threadIdx.x;
    int stride = gridDim.x * blockDim.x;
    const int n4 = (Nn * Hh) / 4;
    float4 z4 = make_float4(0.f, 0.f, 0.f, 0.f);
    for (int i = idx; i < n4; i += stride) {
        reinterpret_cast<float4*>(g_esum)[i] = z4;
        reinterpret_cast<float4*>(g_wsum)[i] = z4;
    }
    for (int i = idx; i < Bb * OUT; i += stride) g_pool[i] = 0.f;
    for (int i = idx; i < Bb; i += stride) g_cnt[i] = 0.f;
    for (int i = idx; i < 3 * 128; i += stride) g_stats[i] = 0.0;
}

// ---------------- 1: node encoder  h = x @ node_w + node_b  [N,64]->[N,32] ----
__global__ void __launch_bounds__(128) enc_kernel(const float* __restrict__ x,
                                                  const float* __restrict__ W,
                                                  const float* __restrict__ bias) {
    __shared__ __align__(16) float zs[64 * 68];
    __shared__ __align__(16) float ws[FIN * Hh];   // 64x32
    int tid = threadIdx.x;
    int n0 = blockIdx.x * 64;
    for (int i = tid; i < FIN * Hh; i += 128) ws[i] = W[i];
    for (int i = tid; i < 64 * FIN; i += 128) {
        int n = i >> 6, k = i & 63;
        int gn = n0 + n;
        zs[n * 68 + k] = (gn < Nn) ? x[(size_t)gn * FIN + k] : 0.f;
    }
    __syncthreads();
    int ti = tid >> 3, tj = tid & 7;           // 16 x 8
    float4 acc0 = {0,0,0,0}, acc1 = {0,0,0,0}, acc2 = {0,0,0,0}, acc3 = {0,0,0,0};
    const float4* ws4 = reinterpret_cast<const float4*>(ws); // [k][8]
    #pragma unroll
    for (int k4 = 0; k4 < 16; k4++) {
        float4 z0 = *reinterpret_cast<const float4*>(zs + (4*ti+0)*68 + 4*k4);
        float4 z1 = *reinterpret_cast<const float4*>(zs + (4*ti+1)*68 + 4*k4);
        float4 z2 = *reinterpret_cast<const float4*>(zs + (4*ti+2)*68 + 4*k4);
        float4 z3 = *reinterpret_cast<const float4*>(zs + (4*ti+3)*68 + 4*k4);
        float4 w0 = ws4[(4*k4+0)*8 + tj];
        float4 w1 = ws4[(4*k4+1)*8 + tj];
        float4 w2 = ws4[(4*k4+2)*8 + tj];
        float4 w3 = ws4[(4*k4+3)*8 + tj];
        fma_row(acc0, z0.x, w0); fma_row(acc0, z0.y, w1); fma_row(acc0, z0.z, w2); fma_row(acc0, z0.w, w3);
        fma_row(acc1, z1.x, w0); fma_row(acc1, z1.y, w1); fma_row(acc1, z1.z, w2); fma_row(acc1, z1.w, w3);
        fma_row(acc2, z2.x, w0); fma_row(acc2, z2.y, w1); fma_row(acc2, z2.z, w2); fma_row(acc2, z2.w, w3);
        fma_row(acc3, z3.x, w0); fma_row(acc3, z3.y, w1); fma_row(acc3, z3.z, w2); fma_row(acc3, z3.w, w3);
    }
    float4 bb = *reinterpret_cast<const float4*>(bias + 4*tj);
    float4 accs[4] = {acc0, acc1, acc2, acc3};
    #pragma unroll
    for (int r = 0; r < 4; r++) {
        int gn = n0 + 4*ti + r;
        if (gn < Nn) {
            float4 v = accs[r];
            v.x += bb.x; v.y += bb.y; v.z += bb.z; v.w += bb.w;
            *reinterpret_cast<float4*>(g_h + (size_t)gn * Hh + 4*tj) = v;
        }
    }
}

// ---------------- 2: edge pass (streamed, 32 edges/tile, reg-capped) ----------
__global__ void __launch_bounds__(256, 4) edge_kernel(const int* __restrict__ ei,
                                                      const float* __restrict__ eattr,
                                                      const float* __restrict__ ew,
                                                      const float* __restrict__ eb) {
    __shared__ __align__(16) float sattr[32 * 20];
    __shared__ __align__(16) float sws[EIN * Hh];   // 16x32
    __shared__ int ssrc[32];
    __shared__ int sdst[32];
    int tid = threadIdx.x;
    for (int i = tid; i < EIN * Hh; i += 256) sws[i] = ew[i];
    int j = tid & 7;          // feature quad (feats 4j..4j+3)
    int el = tid >> 3;        // edge within tile (0..31)
    float4 eb4 = *reinterpret_cast<const float4*>(eb + 4*j);
    const float4* w4p = reinterpret_cast<const float4*>(sws); // [k][8]
    const int ntiles = Ee / 32;
    for (int t = blockIdx.x; t < ntiles; t += gridDim.x) {
        int e0 = t * 32;
        __syncthreads();
        {
            const float2* ap = reinterpret_cast<const float2*>(eattr + (size_t)e0 * EIN);
            float2 v = ap[tid];
            int row = tid >> 3, col = (tid & 7) * 2;
            sattr[row * 20 + col]     = v.x;
            sattr[row * 20 + col + 1] = v.y;
            if (tid < 32) ssrc[tid] = ei[e0 + tid];
            else if (tid < 64) sdst[tid - 32] = ei[Ee + e0 + (tid - 32)];
        }
        __syncthreads();
        int src = ssrc[el], dst = sdst[el];
        float4 ea = eb4;
        const float4* a4p = reinterpret_cast<const float4*>(sattr + el * 20);
        #pragma unroll
        for (int k4 = 0; k4 < 4; k4++) {
            float4 a4 = a4p[k4];
            float4 w0 = w4p[(4*k4+0)*8 + j];
            float4 w1 = w4p[(4*k4+1)*8 + j];
            float4 w2 = w4p[(4*k4+2)*8 + j];
            float4 w3 = w4p[(4*k4+3)*8 + j];
            fma_row(ea, a4.x, w0); fma_row(ea, a4.y, w1); fma_row(ea, a4.z, w2); fma_row(ea, a4.w, w3);
        }
        float4 hv = *reinterpret_cast<const float4*>(g_h + (size_t)src * Hh + 4*j);
        float4 m;
        m.x = fmaxf(hv.x + ea.x, 0.f) + EPS_GEN;
        m.y = fmaxf(hv.y + ea.y, 0.f) + EPS_GEN;
        m.z = fmaxf(hv.z + ea.z, 0.f) + EPS_GEN;
        m.w = fmaxf(hv.w + ea.w, 0.f) + EPS_GEN;
        float4 p;
        p.x = __expf(m.x); p.y = __expf(m.y); p.z = __expf(m.z); p.w = __expf(m.w);
        red_add_v4(g_esum + (size_t)dst * Hh + 4*j, p);
        red_add_v4(g_wsum + (size_t)dst * Hh + 4*j,
                   make_float4(m.x*p.x, m.y*p.y, m.z*p.z, m.w*p.w));
    }
}

// ---------------- 3: stage A  out32 = agg + h ; y1 = out32@W1+b1 ; stats1 ------
__global__ void __launch_bounds__(256) stageA_kernel(const float* __restrict__ W,
                                                     const float* __restrict__ bias) {
    __shared__ __align__(16) float zs[64 * 36];
    __shared__ __align__(16) float ws[Hh * OUT];   // 32x64
    __shared__ float ssum[64], ssq[64];
    int tid = threadIdx.x;
    int n0 = blockIdx.x * 64;
    for (int i = tid; i < Hh * OUT; i += 256) ws[i] = W[i];
    if (tid < 64) { ssum[tid] = 0.f; ssq[tid] = 0.f; }
    for (int i = tid; i < 64 * Hh; i += 256) {
        int n = i >> 5, k = i & 31;
        int gn = n0 + n;
        float z = 0.f;
        if (gn < Nn) {
            float es = g_esum[(size_t)gn * Hh + k];
            float agg = (es > 0.f) ? g_wsum[(size_t)gn * Hh + k] / es : 0.f;
            z = agg + g_h[(size_t)gn * Hh + k];
        }
        zs[n * 36 + k] = z;
    }
    __syncthreads();
    int ti = tid >> 4, tj = tid & 15;
    float4 acc0 = {0,0,0,0}, acc1 = {0,0,0,0}, acc2 = {0,0,0,0}, acc3 = {0,0,0,0};
    const float4* ws4 = reinterpret_cast<const float4*>(ws); // [k][16]
    #pragma unroll
    for (int k4 = 0; k4 < 8; k4++) {
        float4 z0 = *reinterpret_cast<const float4*>(zs + (4*ti+0)*36 + 4*k4);
        float4 z1 = *reinterpret_cast<const float4*>(zs + (4*ti+1)*36 + 4*k4);
        float4 z2 = *reinterpret_cast<const float4*>(zs + (4*ti+2)*36 + 4*k4);
        float4 z3 = *reinterpret_cast<const float4*>(zs + (4*ti+3)*36 + 4*k4);
        float4 w0 = ws4[(4*k4+0)*16 + tj];
        float4 w1 = ws4[(4*k4+1)*16 + tj];
        float4 w2 = ws4[(4*k4+2)*16 + tj];
        float4 w3 = ws4[(4*k4+3)*16 + tj];
        fma_row(acc0, z0.x, w0); fma_row(acc0, z0.y, w1); fma_row(acc0, z0.z, w2); fma_row(acc0, z0.w, w3);
        fma_row(acc1, z1.x, w0); fma_row(acc1, z1.y, w1); fma_row(acc1, z1.z, w2); fma_row(acc1, z1.w, w3);
        fma_row(acc2, z2.x, w0); fma_row(acc2, z2.y, w1); fma_row(acc2, z2.z, w2); fma_row(acc2, z2.w, w3);
        fma_row(acc3, z3.x, w0); fma_row(acc3, z3.y, w1); fma_row(acc3, z3.z, w2); fma_row(acc3, z3.w, w3);
    }
    float4 bb = *reinterpret_cast<const float4*>(bias + 4*tj);
    float4 accs[4] = {acc0, acc1, acc2, acc3};
    float4 ls = {0,0,0,0}, lq = {0,0,0,0};
    #pragma unroll
    for (int r = 0; r < 4; r++) {
        int gn = n0 + 4*ti + r;
        if (gn < Nn) {
            float4 v = accs[r];
            v.x += bb.x; v.y += bb.y; v.z += bb.z; v.w += bb.w;
            *reinterpret_cast<float4*>(g_y1 + (size_t)gn * OUT + 4*tj) = v;
            ls.x += v.x; ls.y += v.y; ls.z += v.z; ls.w += v.w;
            lq.x += v.x*v.x; lq.y += v.y*v.y; lq.z += v.z*v.z; lq.w += v.w*v.w;
        }
    }
    atomicAdd(&ssum[4*tj+0], ls.x); atomicAdd(&ssum[4*tj+1], ls.y);
    atomicAdd(&ssum[4*tj+2], ls.z); atomicAdd(&ssum[4*tj+3], ls.w);
    atomicAdd(&ssq[4*tj+0], lq.x);  atomicAdd(&ssq[4*tj+1], lq.y);
    atomicAdd(&ssq[4*tj+2], lq.z);  atomicAdd(&ssq[4*tj+3], lq.w);
    __syncthreads();
    if (tid < 64) {
        atomicAdd(&g_stats[tid],      (double)ssum[tid]);
        atomicAdd(&g_stats[64 + tid], (double)ssq[tid]);
    }
}

// ---------------- 4: stages B/C  z=relu(bn(in)) ; out=z@W+b ; stats ------------
__global__ void __launch_bounds__(256) stageBC_kernel(const float* __restrict__ W,
                                                      const float* __restrict__ bias,
                                                      const float* __restrict__ gam,
                                                      const float* __restrict__ bet,
                                                      int sel) {
    __shared__ __align__(16) float zs[64 * 68];
    __shared__ __align__(16) float ws[OUT * OUT];  // 64x64
    __shared__ float ssum[64], ssq[64], sscale[64], sshift[64];
    const float* in  = sel ? g_y2 : g_y1;
    float*       out = sel ? g_y3 : g_y2;
    int sin  = sel ? 128 : 0;
    int sout = sel ? 256 : 128;
    int tid = threadIdx.x;
    int n0 = blockIdx.x * 64;
    for (int i = tid; i < OUT * OUT; i += 256) ws[i] = W[i];
    if (tid < 64) {
        double mean = g_stats[sin + tid] / (double)Nn;
        double msq  = g_stats[sin + 64 + tid] / (double)Nn;
        double var  = msq - mean * mean;
        float sc = gam[tid] * rsqrtf((float)var + EPS_BN);
        sscale[tid] = sc;
        sshift[tid] = bet[tid] - (float)mean * sc;
        ssum[tid] = 0.f; ssq[tid] = 0.f;
    }
    __syncthreads();
    for (int i = tid; i < 64 * OUT; i += 256) {
        int n = i >> 6, k = i & 63;
        int gn = n0 + n;
        float z = 0.f;
        if (gn < Nn) z = fmaxf(sscale[k] * in[(size_t)gn * OUT + k] + sshift[k], 0.f);
        zs[n * 68 + k] = z;
    }
    __syncthreads();
    int ti = tid >> 4, tj = tid & 15;
    float4 acc0 = {0,0,0,0}, acc1 = {0,0,0,0}, acc2 = {0,0,0,0}, acc3 = {0,0,0,0};
    const float4* ws4 = reinterpret_cast<const float4*>(ws);
    #pragma unroll
    for (int k4 = 0; k4 < 16; k4++) {
        float4 z0 = *reinterpret_cast<const float4*>(zs + (4*ti+0)*68 + 4*k4);
        float4 z1 = *reinterpret_cast<const float4*>(zs + (4*ti+1)*68 + 4*k4);
        float4 z2 = *reinterpret_cast<const float4*>(zs + (4*ti+2)*68 + 4*k4);
        float4 z3 = *reinterpret_cast<const float4*>(zs + (4*ti+3)*68 + 4*k4);
        float4 w0 = ws4[(4*k4+0)*16 + tj];
        float4 w1 = ws4[(4*k4+1)*16 + tj];
        float4 w2 = ws4[(4*k4+2)*16 + tj];
        float4 w3 = ws4[(4*k4+3)*16 + tj];
        fma_row(acc0, z0.x, w0); fma_row(acc0, z0.y, w1); fma_row(acc0, z0.z, w2); fma_row(acc0, z0.w, w3);
        fma_row(acc1, z1.x, w0); fma_row(acc1, z1.y, w1); fma_row(acc1, z1.z, w2); fma_row(acc1, z1.w, w3);
        fma_row(acc2, z2.x, w0); fma_row(acc2, z2.y, w1); fma_row(acc2, z2.z, w2); fma_row(acc2, z2.w, w3);
        fma_row(acc3, z3.x, w0); fma_row(acc3, z3.y, w1); fma_row(acc3, z3.z, w2); fma_row(acc3, z3.w, w3);
    }
    float4 bb = *reinterpret_cast<const float4*>(bias + 4*tj);
    float4 accs[4] = {acc0, acc1, acc2, acc3};
    float4 ls = {0,0,0,0}, lq = {0,0,0,0};
    #pragma unroll
    for (int r = 0; r < 4; r++) {
        int gn = n0 + 4*ti + r;
        if (gn < Nn) {
            float4 v = accs[r];
            v.x += bb.x; v.y += bb.y; v.z += bb.z; v.w += bb.w;
            *reinterpret_cast<float4*>(out + (size_t)gn * OUT + 4*tj) = v;
            ls.x += v.x; ls.y += v.y; ls.z += v.z; ls.w += v.w;
            lq.x += v.x*v.x; lq.y += v.y*v.y; lq.z += v.z*v.z; lq.w += v.w*v.w;
        }
    }
    atomicAdd(&ssum[4*tj+0], ls.x); atomicAdd(&ssum[4*tj+1], ls.y);
    atomicAdd(&ssum[4*tj+2], ls.z); atomicAdd(&ssum[4*tj+3], ls.w);
    atomicAdd(&ssq[4*tj+0], lq.x);  atomicAdd(&ssq[4*tj+1], lq.y);
    atomicAdd(&ssq[4*tj+2], lq.z);  atomicAdd(&ssq[4*tj+3], lq.w);
    __syncthreads();
    if (tid < 64) {
        atomicAdd(&g_stats[sout + tid],      (double)ssum[tid]);
        atomicAdd(&g_stats[sout + 64 + tid], (double)ssq[tid]);
    }
}

// ---------------- 5: stage D  node_out = relu(bn3(y3))@W4+b4, pooled -----------
__global__ void __launch_bounds__(256) stageD_kernel(const float* __restrict__ W,
                                                     const float* __restrict__ bias,
                                                     const float* __restrict__ gam,
                                                     const float* __restrict__ bet,
                                                     const int* __restrict__ batch) {
    __shared__ __align__(16) float zs[64 * 68];
    __shared__ __align__(16) float ws[OUT * OUT];
    __shared__ float sscale[64], sshift[64];
    int tid = threadIdx.x;
    int n0 = blockIdx.x * 64;
    for (int i = tid; i < OUT * OUT; i += 256) ws[i] = W[i];
    if (tid < 64) {
        double mean = g_stats[256 + tid] / (double)Nn;
        double msq  = g_stats[256 + 64 + tid] / (double)Nn;
        double var  = msq - mean * mean;
        float sc = gam[tid] * rsqrtf((float)var + EPS_BN);
        sscale[tid] = sc;
        sshift[tid] = bet[tid] - (float)mean * sc;
    }
    __syncthreads();
    for (int i = tid; i < 64 * OUT; i += 256) {
        int n = i >> 6, k = i & 63;
        int gn = n0 + n;
        float z = 0.f;
        if (gn < Nn) z = fmaxf(sscale[k] * g_y3[(size_t)gn * OUT + k] + sshift[k], 0.f);
        zs[n * 68 + k] = z;
    }
    __syncthreads();
    int ti = tid >> 4, tj = tid & 15;
    float4 acc0 = {0,0,0,0}, acc1 = {0,0,0,0}, acc2 = {0,0,0,0}, acc3 = {0,0,0,0};
    const float4* ws4 = reinterpret_cast<const float4*>(ws);
    #pragma unroll
    for (int k4 = 0; k4 < 16; k4++) {
        float4 z0 = *reinterpret_cast<const float4*>(zs + (4*ti+0)*68 + 4*k4);
        float4 z1 = *reinterpret_cast<const float4*>(zs + (4*ti+1)*68 + 4*k4);
        float4 z2 = *reinterpret_cast<const float4*>(zs + (4*ti+2)*68 + 4*k4);
        float4 z3 = *reinterpret_cast<const float4*>(zs + (4*ti+3)*68 + 4*k4);
        float4 w0 = ws4[(4*k4+0)*16 + tj];
        float4 w1 = ws4[(4*k4+1)*16 + tj];
        float4 w2 = ws4[(4*k4+2)*16 + tj];
        float4 w3 = ws4[(4*k4+3)*16 + tj];
        fma_row(acc0, z0.x, w0); fma_row(acc0, z0.y, w1); fma_row(acc0, z0.z, w2); fma_row(acc0, z0.w, w3);
        fma_row(acc1, z1.x, w0); fma_row(acc1, z1.y, w1); fma_row(acc1, z1.z, w2); fma_row(acc1, z1.w, w3);
        fma_row(acc2, z2.x, w0); fma_row(acc2, z2.y, w1); fma_row(acc2, z2.z, w2); fma_row(acc2, z2.w, w3);
        fma_row(acc3, z3.x, w0); fma_row(acc3, z3.y, w1); fma_row(acc3, z3.z, w2); fma_row(acc3, z3.w, w3);
    }
    float4 bb = *reinterpret_cast<const float4*>(bias + 4*tj);
    float4 accs[4] = {acc0, acc1, acc2, acc3};
    #pragma unroll
    for (int r = 0; r < 4; r++) {
        int gn = n0 + 4*ti + r;
        if (gn < Nn) {
            float4 v = accs[r];
            v.x += bb.x; v.y += bb.y; v.z += bb.z; v.w += bb.w;
            int g = batch[gn];
            red_add_v4(&g_pool[(size_t)g * OUT + 4*tj], v);
            if (tj == 0) atomicAdd(&g_cnt[g], 1.0f);
        }
    }
}

// ---------------- 6: head (per graph) -----------------------------------------
__global__ void head_kernel(const float* __restrict__ action,
                            const float* __restrict__ pinw, const float* __restrict__ pinb,
                            const float* __restrict__ phw,  const float* __restrict__ phb,
                            const float* __restrict__ pow_, const float* __restrict__ pob,
                            float* __restrict__ outp) {
    int g = threadIdx.x;
    if (g >= Bb) return;
    float inv = 1.0f / fmaxf(g_cnt[g], 1.0f);
    float fp[16];
    #pragma unroll
    for (int jj = 0; jj < 16; jj++) {
        float s = 0.f;
        for (int f = 0; f < OUT; f++) s += g_pool[g * OUT + f] * pinw[f * 16 + jj];
        fp[jj] = fmaxf(s * inv + pinb[jj], 0.f);
    }
    float res = pob[0];
    #pragma unroll
    for (int q = 0; q < 10; q++) {
        float s = phb[q];
        #pragma unroll
        for (int jj = 0; jj < 16; jj++) s += fp[jj] * phw[jj * 10 + q];
        #pragma unroll
        for (int a = 0; a < ADIM; a++) s += action[g * ADIM + a] * phw[(16 + a) * 10 + q];
        res += fmaxf(s, 0.f) * pow_[q];
    }
    outp[g] = res;
}

// ---------------- launch -------------------------------------------------------
extern "C" void kernel_launch(void* const* d_in, const int* in_sizes, int n_in,
                              void* d_out, int out_size) {
    const float* x      = (const float*)d_in[0];
    const int*   ei     = (const int*)  d_in[1];
    const float* eattr  = (const float*)d_in[2];
    const int*   batch  = (const int*)  d_in[3];
    const float* action = (const float*)d_in[4];
    const float* node_w = (const float*)d_in[5];
    const float* node_b = (const float*)d_in[6];
    const float* edge_w = (const float*)d_in[7];
    const float* edge_b = (const float*)d_in[8];
    const float* w1 = (const float*)d_in[9];  const float* b1 = (const float*)d_in[10];
    const float* g1 = (const float*)d_in[11]; const float* bb1 = (const float*)d_in[12];
    const float* w2 = (const float*)d_in[13]; const float* b2 = (const float*)d_in[14];
    const float* g2 = (const float*)d_in[15]; const float* bb2 = (const float*)d_in[16];
    const float* w3 = (const float*)d_in[17]; const float* b3 = (const float*)d_in[18];
    const float* g3 = (const float*)d_in[19]; const float* bb3 = (const float*)d_in[20];
    const float* w4 = (const float*)d_in[21]; const float* b4 = (const float*)d_in[22];
    const float* pinw = (const float*)d_in[23]; const float* pinb = (const float*)d_in[24];
    const float* phw  = (const float*)d_in[25]; const float* phb  = (const float*)d_in[26];
    const float* pow_ = (const float*)d_in[27]; const float* pob  = (const float*)d_in[28];

    const int NBLK = (Nn + 63) / 64;  // 1563

    zero_kernel<<<2048, 256>>>();                       // 1
    enc_kernel<<<NBLK, 128>>>(x, node_w, node_b);       // 2
    noop_kernel<<<1, 32>>>();                           // 3
    edge_kernel<<<2048, 256>>>(ei, eattr, edge_w, edge_b); // 4 <- ncu captures this
    stageA_kernel<<<NBLK, 256>>>(w1, b1);
    stageBC_kernel<<<NBLK, 256>>>(w2, b2, g1, bb1, 0);
    stageBC_kernel<<<NBLK, 256>>>(w3, b3, g2, bb2, 1);
    stageD_kernel<<<NBLK, 256>>>(w4, b4, g3, bb3, batch);
    head_kernel<<<1, 64>>>(action, pinw, pinb, phw, phb, pow_, pob, (float*)d_out);
}